// round 1
// baseline (speedup 1.0000x reference)
#include <cuda_runtime.h>
#include <math.h>

// Problem constants (fixed by the bench instance)
#define BB   2
#define LQ_  2048
#define LK_  2048
#define HID_ 1024
#define NH_  16
#define HD_  64

// ---------------- scratch (device globals: no allocation allowed) -----------
__device__ float g_tmpq [BB*LQ_*HID_];      // q proj output (scaled, pre-RoPE)
__device__ float g_tmpkv[BB*LK_*2*HID_];    // kv proj output
__device__ float g_q [BB*NH_*LQ_*HD_];      // RoPE'd q, [b][h][t][d]
__device__ float g_k [BB*NH_*LK_*HD_];      // RoPE'd + dist-emb k, [b][h][t][d]
__device__ float g_v [BB*NH_*LK_*HD_];      // v, [b][h][t][d]
__device__ float g_att[BB*LQ_*HID_];        // attention output, [b][t][hid]
__device__ int   g_boundq[BB*LQ_];
__device__ int   g_boundk[BB*LK_];
__device__ float g_posq[BB*LQ_];
__device__ float g_posk[BB*LK_];
__device__ float g_distk[BB*LK_];
__device__ int   g_validq[BB*LQ_];
__device__ int   g_validk[BB*LK_];

// ---------------- segment positions (replicates _subseq_positions) ----------
__global__ void cumsum_kernel(const int* __restrict__ mask, int* __restrict__ bound, int L) {
    if (threadIdx.x == 0) {
        const int* m = mask + blockIdx.x * L;
        int* bo = bound + blockIdx.x * L;
        int s = 0;
        for (int i = 0; i < L; ++i) { s += m[i]; bo[i] = s; }
    }
}

__global__ void posval_kernel(const int* __restrict__ mask, const int* __restrict__ bound,
                              const float* __restrict__ distances,
                              float* __restrict__ pos, int* __restrict__ valid,
                              float* __restrict__ dist, int L) {
    int idx = blockIdx.x * blockDim.x + threadIdx.x;
    int total = BB * L;
    if (idx >= total) return;
    int b = idx / L, t = idx - b * L;
    const int* bo = bound + b * L;
    // searchsorted(bo, t, side='right'): first i with bo[i] > t
    int lo = 0, hi = L;
    while (lo < hi) { int mid = (lo + hi) >> 1; if (bo[mid] <= t) lo = mid + 1; else hi = mid; }
    int seg = lo < (L - 1) ? lo : (L - 1);
    int v = (t < bo[L - 1]) ? 1 : 0;
    int start = bo[seg] - mask[b * L + seg];
    pos[idx] = v ? (float)(t - start) : 0.0f;
    valid[idx] = v;
    if (dist) dist[idx] = v ? distances[b * L + seg] : 0.0f;
}

// ---------------- generic tiled SGEMM: C = (A@B + bias) * scale -------------
// A: MxK row-major, B: KxN row-major, bias: N. Tiles 64x64x16, 256 threads, 4x4 per thread.
__global__ __launch_bounds__(256) void sgemm_kernel(
    const float* __restrict__ A, const float* __restrict__ Bm,
    const float* __restrict__ bias, float* __restrict__ C,
    int M, int N, int K, float scale)
{
    __shared__ float As[64][17];   // padded: conflict-free column reads
    __shared__ float Bs[16][64];
    const int bm = blockIdx.y * 64, bn = blockIdx.x * 64;
    const int tid = threadIdx.x;
    const int ti = tid >> 4, tj = tid & 15;
    float acc[4][4] = {};

    for (int k0 = 0; k0 < K; k0 += 16) {
        #pragma unroll
        for (int i = 0; i < 4; ++i) {
            int idx = tid + i * 256;               // 0..1023
            int r = idx >> 4, c = idx & 15;        // A tile 64x16
            As[r][c] = A[(size_t)(bm + r) * K + k0 + c];
            int rb = idx >> 6, cb = idx & 63;      // B tile 16x64
            Bs[rb][cb] = Bm[(size_t)(k0 + rb) * N + bn + cb];
        }
        __syncthreads();
        #pragma unroll
        for (int k = 0; k < 16; ++k) {
            float a[4];
            #pragma unroll
            for (int ii = 0; ii < 4; ++ii) a[ii] = As[ti * 4 + ii][k];
            float4 bv = *(const float4*)&Bs[k][tj * 4];
            float bb[4] = {bv.x, bv.y, bv.z, bv.w};
            #pragma unroll
            for (int ii = 0; ii < 4; ++ii)
                #pragma unroll
                for (int jj = 0; jj < 4; ++jj)
                    acc[ii][jj] += a[ii] * bb[jj];
        }
        __syncthreads();
    }
    #pragma unroll
    for (int ii = 0; ii < 4; ++ii) {
        int r = bm + ti * 4 + ii;
        #pragma unroll
        for (int jj = 0; jj < 4; ++jj) {
            int c = bn + tj * 4 + jj;
            C[(size_t)r * N + c] = (acc[ii][jj] + bias[c]) * scale;
        }
    }
}

// ---------------- RoPE for Q (scale already applied in GEMM) ----------------
// idx over B*LQ*HID:  d=idx&63, h=(idx>>6)&15, t=(idx>>10)&2047, b=idx>>21
__global__ void rope_q_kernel(const float* __restrict__ tmpq,
                              const float* __restrict__ posq,
                              float* __restrict__ qout) {
    int idx = blockIdx.x * blockDim.x + threadIdx.x;
    if (idx >= BB * LQ_ * HID_) return;
    int d = idx & 63;
    int h = (idx >> 6) & 15;
    int t = (idx >> 10) & 2047;
    int b = idx >> 21;
    float x  = tmpq[idx];
    float xp = tmpq[idx ^ 32];                      // rotate_half partner
    float rh = (d < 32) ? -xp : xp;
    float p  = posq[b * LQ_ + t];
    int j = d & 31;
    float invf = expf(-(float)j * 0.28782313662425572f);   // ln(10000)/32
    float ph = p * invf;
    float out = x * cosf(ph) + rh * sinf(ph);
    qout[(((size_t)(b * NH_ + h)) * LQ_ + t) * HD_ + d] = out;
}

// ---------------- RoPE + distance-emb for K, relayout V ---------------------
__global__ void rope_kv_kernel(const float* __restrict__ tmpkv,
                               const float* __restrict__ posk,
                               const float* __restrict__ distk,
                               float* __restrict__ kout,
                               float* __restrict__ vout) {
    int idx = blockIdx.x * blockDim.x + threadIdx.x;
    if (idx >= BB * LK_ * HID_) return;
    int d = idx & 63;
    int h = (idx >> 6) & 15;
    int t = (idx >> 10) & 2047;
    int b = idx >> 21;
    size_t rowbase = ((size_t)b * LK_ + t) * (2 * HID_);
    int hd = h * 64 + d;
    float x  = tmpkv[rowbase + hd];
    float xp = tmpkv[rowbase + (hd ^ 32)];
    float rh = (d < 32) ? -xp : xp;
    float p  = posk[b * LK_ + t];
    int j = d & 31;
    float invf = expf(-(float)j * 0.28782313662425572f);
    float ph = p * invf;
    // geomspace(1e-5, 0.25, 32): f_j = exp(ln(1e-5) + j*(ln0.25-ln1e-5)/31)
    int dj = (d < 32) ? d : d - 32;
    float fg = expf(-11.512925464970229f + (float)dj * 0.32666551948001156f);
    float dist = distk[b * LK_ + t];
    float arg = dist * fg;
    float demb = (d < 32) ? cosf(arg) : sinf(arg);
    float kr = x * cosf(ph) + rh * sinf(ph) + demb;
    size_t o = (((size_t)(b * NH_ + h)) * LK_ + t) * HD_ + d;
    kout[o] = kr;
    vout[o] = tmpkv[rowbase + HID_ + hd];
}

// ---------------- flash attention, fp32 -------------------------------------
// Block: 64 q-rows x full K loop, 256 threads, 4x4 tile/thread.
// smem: Qs[64][68] (d-major), Ps[64][68] (K tile d-major, reused as P r-major),
//       Vs[64][64] (row-major), stats 4*64.
#define AT_PAD 68
__global__ __launch_bounds__(256) void attn_kernel(
    const float* __restrict__ Qg, const float* __restrict__ Kg,
    const float* __restrict__ Vg, const int* __restrict__ validk,
    const int* __restrict__ validq, float* __restrict__ Og)
{
    extern __shared__ float sm[];
    float* Qs   = sm;                    // 64*68  (Qs[d*68 + r])
    float* Ps   = Qs + 64 * AT_PAD;      // 64*68  (K tile as Ps[d*68+c], then P as Ps[r*68+c])
    float* Vs   = Ps + 64 * AT_PAD;      // 64*64  (Vs[j*64 + d])
    float* rowm = Vs + 64 * 64;
    float* rowl = rowm + 64;
    float* alph = rowl + 64;
    float* madd = alph + 64;

    const int qt = blockIdx.x, h = blockIdx.y, b = blockIdx.z;
    const int tid = threadIdx.x;
    const int ti = tid >> 4, tj = tid & 15;
    const float* Qb = Qg + (((size_t)(b * NH_ + h)) * LQ_ + qt * 64) * HD_;
    const float* Kb = Kg + ((size_t)(b * NH_ + h)) * LK_ * HD_;
    const float* Vb = Vg + ((size_t)(b * NH_ + h)) * LK_ * HD_;

    // load Q tile transposed (d-major)
    #pragma unroll
    for (int i = 0; i < 16; ++i) {
        int idx = tid + i * 256;            // 0..4095
        int r = idx >> 6, d = idx & 63;
        Qs[d * AT_PAD + r] = Qb[idx];       // Qb[r*64+d] == Qb[idx]
    }
    if (tid < 64) { rowm[tid] = -1e30f; rowl[tid] = 0.0f; }
    float O[4][4] = {};
    __syncthreads();

    for (int kt = 0; kt < LK_ / 64; ++kt) {
        const float* Kt = Kb + (size_t)kt * 64 * HD_;
        const float* Vt = Vb + (size_t)kt * 64 * HD_;
        #pragma unroll
        for (int i = 0; i < 16; ++i) {
            int idx = tid + i * 256;
            int r = idx >> 6, d = idx & 63;
            Ps[d * AT_PAD + r] = Kt[idx];
            Vs[idx] = Vt[idx];
        }
        if (tid < 64)
            madd[tid] = validk[b * LK_ + kt * 64 + tid] ? 0.0f : -1e9f;
        __syncthreads();

        // S = Q K^T  (64 d-steps, float4 smem reads)
        float S[4][4] = {};
        #pragma unroll 8
        for (int d = 0; d < 64; ++d) {
            float4 aq = *(const float4*)(Qs + d * AT_PAD + ti * 4);
            float4 bk = *(const float4*)(Ps + d * AT_PAD + tj * 4);
            float a[4] = {aq.x, aq.y, aq.z, aq.w};
            float bb[4] = {bk.x, bk.y, bk.z, bk.w};
            #pragma unroll
            for (int ii = 0; ii < 4; ++ii)
                #pragma unroll
                for (int jj = 0; jj < 4; ++jj)
                    S[ii][jj] += a[ii] * bb[jj];
        }
        __syncthreads();  // done reading K tile -> safe to overwrite with P

        #pragma unroll
        for (int ii = 0; ii < 4; ++ii)
            #pragma unroll
            for (int jj = 0; jj < 4; ++jj)
                Ps[(ti * 4 + ii) * AT_PAD + tj * 4 + jj] = S[ii][jj] + madd[tj * 4 + jj];
        __syncthreads();

        // online softmax, one thread per row
        if (tid < 64) {
            const int r = tid;
            float m = rowm[r], mx = m;
            #pragma unroll 8
            for (int j = 0; j < 64; ++j) mx = fmaxf(mx, Ps[r * AT_PAD + j]);
            float al = expf(m - mx);           // first iter: exp(-1e30 - mx) = 0
            float l = rowl[r] * al;
            #pragma unroll 8
            for (int j = 0; j < 64; ++j) {
                float p = expf(Ps[r * AT_PAD + j] - mx);
                Ps[r * AT_PAD + j] = p;
                l += p;
            }
            rowm[r] = mx; rowl[r] = l; alph[r] = al;
        }
        __syncthreads();

        // rescale + O += P V
        float al[4];
        #pragma unroll
        for (int ii = 0; ii < 4; ++ii) al[ii] = alph[ti * 4 + ii];
        #pragma unroll
        for (int ii = 0; ii < 4; ++ii)
            #pragma unroll
            for (int jj = 0; jj < 4; ++jj) O[ii][jj] *= al[ii];
        #pragma unroll 4
        for (int j = 0; j < 64; ++j) {
            float4 vv = *(const float4*)(Vs + j * 64 + tj * 4);
            float vr[4] = {vv.x, vv.y, vv.z, vv.w};
            float pr[4];
            #pragma unroll
            for (int ii = 0; ii < 4; ++ii) pr[ii] = Ps[(ti * 4 + ii) * AT_PAD + j];
            #pragma unroll
            for (int ii = 0; ii < 4; ++ii)
                #pragma unroll
                for (int jj = 0; jj < 4; ++jj)
                    O[ii][jj] += pr[ii] * vr[jj];
        }
        __syncthreads();  // protect smem before next tile load
    }

    // epilogue: divide by l, zero invalid q rows, write [b][t][h*64+d]
    #pragma unroll
    for (int ii = 0; ii < 4; ++ii) {
        int r = ti * 4 + ii;
        int tg = qt * 64 + r;
        float inv = 1.0f / rowl[r];
        int vq = validq[b * LQ_ + tg];
        size_t ob = ((size_t)(b * LQ_) + tg) * HID_ + h * 64 + tj * 4;
        #pragma unroll
        for (int jj = 0; jj < 4; ++jj)
            Og[ob + jj] = vq ? O[ii][jj] * inv : 0.0f;
    }
}

// ---------------- launch --------------------------------------------------
extern "C" void kernel_launch(void* const* d_in, const int* in_sizes, int n_in,
                              void* d_out, int out_size) {
    const float* q_states  = (const float*)d_in[0];
    const float* kv_states = (const float*)d_in[1];
    const float* distances = (const float*)d_in[2];
    const int*   mask_q    = (const int*)d_in[3];
    const int*   mask_kv   = (const int*)d_in[4];
    const float* Wq        = (const float*)d_in[5];
    const float* bq        = (const float*)d_in[6];
    const float* Wkv       = (const float*)d_in[7];
    const float* bkv       = (const float*)d_in[8];
    const float* Wo        = (const float*)d_in[9];
    const float* bo        = (const float*)d_in[10];
    float* out = (float*)d_out;

    float *p_tmpq, *p_tmpkv, *p_q, *p_k, *p_v, *p_att, *p_posq, *p_posk, *p_distk;
    int *p_boundq, *p_boundk, *p_validq, *p_validk;
    cudaGetSymbolAddress((void**)&p_tmpq,  g_tmpq);
    cudaGetSymbolAddress((void**)&p_tmpkv, g_tmpkv);
    cudaGetSymbolAddress((void**)&p_q,     g_q);
    cudaGetSymbolAddress((void**)&p_k,     g_k);
    cudaGetSymbolAddress((void**)&p_v,     g_v);
    cudaGetSymbolAddress((void**)&p_att,   g_att);
    cudaGetSymbolAddress((void**)&p_posq,  g_posq);
    cudaGetSymbolAddress((void**)&p_posk,  g_posk);
    cudaGetSymbolAddress((void**)&p_distk, g_distk);
    cudaGetSymbolAddress((void**)&p_boundq, g_boundq);
    cudaGetSymbolAddress((void**)&p_boundk, g_boundk);
    cudaGetSymbolAddress((void**)&p_validq, g_validq);
    cudaGetSymbolAddress((void**)&p_validk, g_validk);

    // segment geometry
    cumsum_kernel<<<BB, 32>>>(mask_q,  p_boundq, LQ_);
    cumsum_kernel<<<BB, 32>>>(mask_kv, p_boundk, LK_);
    posval_kernel<<<(BB * LQ_ + 255) / 256, 256>>>(mask_q,  p_boundq, nullptr,   p_posq, p_validq, nullptr, LQ_);
    posval_kernel<<<(BB * LK_ + 255) / 256, 256>>>(mask_kv, p_boundk, distances, p_posk, p_validk, p_distk, LK_);

    // projections
    dim3 gq(HID_ / 64, BB * LQ_ / 64);
    sgemm_kernel<<<gq, 256>>>(q_states, Wq, bq, p_tmpq, BB * LQ_, HID_, HID_, 0.125f);  // hd^-0.5
    dim3 gkv(2 * HID_ / 64, BB * LK_ / 64);
    sgemm_kernel<<<gkv, 256>>>(kv_states, Wkv, bkv, p_tmpkv, BB * LK_, 2 * HID_, HID_, 1.0f);

    // RoPE / distance emb / relayout
    rope_q_kernel <<<BB * LQ_ * HID_ / 256, 256>>>(p_tmpq, p_posq, p_q);
    rope_kv_kernel<<<BB * LK_ * HID_ / 256, 256>>>(p_tmpkv, p_posk, p_distk, p_k, p_v);

    // attention
    size_t smem = (size_t)(64 * AT_PAD * 2 + 64 * 64 + 4 * 64) * sizeof(float);  // 52224 B
    cudaFuncSetAttribute(attn_kernel, cudaFuncAttributeMaxDynamicSharedMemorySize, (int)smem);
    attn_kernel<<<dim3(LQ_ / 64, NH_, BB), 256, smem>>>(p_q, p_k, p_v, p_validk, p_validq, p_att);

    // output projection
    sgemm_kernel<<<gq, 256>>>(p_att, Wo, bo, out, BB * LQ_, HID_, HID_, 1.0f);
}

// round 2
// speedup vs baseline: 1.8161x; 1.8161x over previous
#include <cuda_runtime.h>
#include <math.h>

#define BB   2
#define LQ_  2048
#define LK_  2048
#define HID_ 1024
#define NH_  16
#define HD_  64

// ---------------- scratch ----------------------------------------------------
__device__ float g_tmpq [BB*LQ_*HID_];
__device__ float g_tmpkv[BB*LK_*2*HID_];
__device__ float g_q [BB*NH_*LQ_*HD_];
__device__ float g_k [BB*NH_*LK_*HD_];
__device__ float g_v [BB*NH_*LK_*HD_];
__device__ float g_att[BB*LQ_*HID_];
__device__ int   g_boundq[BB*LQ_];
__device__ int   g_boundk[BB*LK_];
__device__ float g_posq[BB*LQ_];
__device__ float g_posk[BB*LK_];
__device__ float g_distk[BB*LK_];
__device__ int   g_validq[BB*LQ_];
__device__ int   g_validk[BB*LK_];

// ---------------- tf32 helpers ----------------------------------------------
__device__ __forceinline__ unsigned f2tf(float x) {
    unsigned r;
    asm("cvt.rna.tf32.f32 %0, %1;" : "=r"(r) : "f"(x));
    return r;
}

__device__ __forceinline__ void mma8(float* c, const unsigned* a, const unsigned* b) {
    asm volatile(
        "mma.sync.aligned.m16n8k8.row.col.f32.tf32.tf32.f32 "
        "{%0,%1,%2,%3}, {%4,%5,%6,%7}, {%8,%9}, {%0,%1,%2,%3};"
        : "+f"(c[0]), "+f"(c[1]), "+f"(c[2]), "+f"(c[3])
        : "r"(a[0]), "r"(a[1]), "r"(a[2]), "r"(a[3]), "r"(b[0]), "r"(b[1]));
}

// ---------------- segment geometry ------------------------------------------
__global__ void cumsum_kernel(const int* __restrict__ mask, int* __restrict__ bound, int L) {
    __shared__ int s[LK_];
    int b = blockIdx.x;
    for (int i = threadIdx.x; i < L; i += blockDim.x) s[i] = mask[b * L + i];
    __syncthreads();
    for (int i = threadIdx.x; i < L; i += blockDim.x) {
        int acc = 0;
        for (int j = 0; j <= i; ++j) acc += s[j];
        bound[b * L + i] = acc;
    }
}

__global__ void posval_kernel(const int* __restrict__ mask, const int* __restrict__ bound,
                              const float* __restrict__ distances,
                              float* __restrict__ pos, int* __restrict__ valid,
                              float* __restrict__ dist, int L) {
    int idx = blockIdx.x * blockDim.x + threadIdx.x;
    if (idx >= BB * L) return;
    int b = idx / L, t = idx - b * L;
    const int* bo = bound + b * L;
    int lo = 0, hi = L;
    while (lo < hi) { int mid = (lo + hi) >> 1; if (bo[mid] <= t) lo = mid + 1; else hi = mid; }
    int seg = lo < (L - 1) ? lo : (L - 1);
    int v = (t < bo[L - 1]) ? 1 : 0;
    int start = bo[seg] - mask[b * L + seg];
    pos[idx] = v ? (float)(t - start) : 0.0f;
    valid[idx] = v;
    if (dist) dist[idx] = v ? distances[b * L + seg] : 0.0f;
}

// ---------------- TF32 tensor-core GEMM: C = (A@B + bias) * scale -----------
// A: MxK row-major, B: KxN row-major. CTA tile 128x128, k-chunk 16.
// Smem: As[row][20] (tf32 bits), Bs[k][136]. Fragment LDS bank-conflict-free.
#define GLDA 20
#define GLDB 136
__global__ __launch_bounds__(256) void tgemm_kernel(
    const float* __restrict__ A, const float* __restrict__ Bm,
    const float* __restrict__ bias, float* __restrict__ C,
    int M, int N, int K, float scale)
{
    __shared__ unsigned As[128 * GLDA];
    __shared__ unsigned Bs[16 * GLDB];
    const int tid = threadIdx.x, lane = tid & 31, wid = tid >> 5;
    const int wm = wid >> 2, wn = wid & 3;       // 2x4 warp grid: 64 rows x 32 cols each
    const int r = lane >> 2, c = lane & 3;
    const int bm = blockIdx.y * 128, bn = blockIdx.x * 128;
    const float* Ag = A + (size_t)bm * K;

    float acc[4][4][4] = {};
    float4 pa[2], pb[2];

    auto ldchunk = [&](int k0) {
        #pragma unroll
        for (int j = 0; j < 2; ++j) {
            int idx = tid + j * 256;                    // 0..511 float4s of A tile
            int row = idx >> 2, kq = (idx & 3) * 4;
            pa[j] = *(const float4*)(Ag + (size_t)row * K + k0 + kq);
        }
        #pragma unroll
        for (int j = 0; j < 2; ++j) {
            int idx = tid + j * 256;                    // 0..511 float4s of B tile
            int kk = idx >> 5, n4 = (idx & 31) * 4;
            pb[j] = *(const float4*)(Bm + (size_t)(k0 + kk) * N + bn + n4);
        }
    };
    auto stchunk = [&]() {
        #pragma unroll
        for (int j = 0; j < 2; ++j) {
            int idx = tid + j * 256;
            int row = idx >> 2, kq = (idx & 3) * 4;
            unsigned* p = &As[row * GLDA + kq];
            p[0] = f2tf(pa[j].x); p[1] = f2tf(pa[j].y); p[2] = f2tf(pa[j].z); p[3] = f2tf(pa[j].w);
        }
        #pragma unroll
        for (int j = 0; j < 2; ++j) {
            int idx = tid + j * 256;
            int kk = idx >> 5, n4 = (idx & 31) * 4;
            unsigned* p = &Bs[kk * GLDB + n4];
            p[0] = f2tf(pb[j].x); p[1] = f2tf(pb[j].y); p[2] = f2tf(pb[j].z); p[3] = f2tf(pb[j].w);
        }
    };

    ldchunk(0);
    stchunk();
    __syncthreads();

    for (int k0 = 16; k0 <= K; k0 += 16) {
        if (k0 < K) ldchunk(k0);
        #pragma unroll
        for (int ks = 0; ks < 2; ++ks) {
            unsigned af[4][4], bf[4][2];
            #pragma unroll
            for (int mt = 0; mt < 4; ++mt) {
                int base = (wm * 64 + mt * 16 + r) * GLDA + ks * 8 + c;
                af[mt][0] = As[base];
                af[mt][1] = As[base + 8 * GLDA];
                af[mt][2] = As[base + 4];
                af[mt][3] = As[base + 8 * GLDA + 4];
            }
            #pragma unroll
            for (int nt = 0; nt < 4; ++nt) {
                int n0 = wn * 32 + nt * 8 + r;
                int kc = ks * 8 + c;
                bf[nt][0] = Bs[kc * GLDB + n0];
                bf[nt][1] = Bs[(kc + 4) * GLDB + n0];
            }
            #pragma unroll
            for (int mt = 0; mt < 4; ++mt)
                #pragma unroll
                for (int nt = 0; nt < 4; ++nt)
                    mma8(acc[mt][nt], af[mt], bf[nt]);
        }
        __syncthreads();
        if (k0 < K) { stchunk(); __syncthreads(); }
    }

    #pragma unroll
    for (int mt = 0; mt < 4; ++mt) {
        #pragma unroll
        for (int nt = 0; nt < 4; ++nt) {
            int row = bm + wm * 64 + mt * 16 + r;
            int cc  = bn + wn * 32 + nt * 8 + 2 * c;
            float b0 = bias[cc], b1 = bias[cc + 1];
            C[(size_t)row * N + cc]           = (acc[mt][nt][0] + b0) * scale;
            C[(size_t)row * N + cc + 1]       = (acc[mt][nt][1] + b1) * scale;
            C[(size_t)(row + 8) * N + cc]     = (acc[mt][nt][2] + b0) * scale;
            C[(size_t)(row + 8) * N + cc + 1] = (acc[mt][nt][3] + b1) * scale;
        }
    }
}

// ---------------- RoPE kernels (unchanged from R1) ---------------------------
__global__ void rope_q_kernel(const float* __restrict__ tmpq,
                              const float* __restrict__ posq,
                              float* __restrict__ qout) {
    int idx = blockIdx.x * blockDim.x + threadIdx.x;
    if (idx >= BB * LQ_ * HID_) return;
    int d = idx & 63;
    int h = (idx >> 6) & 15;
    int t = (idx >> 10) & 2047;
    int b = idx >> 21;
    float x  = tmpq[idx];
    float xp = tmpq[idx ^ 32];
    float rh = (d < 32) ? -xp : xp;
    float p  = posq[b * LQ_ + t];
    int j = d & 31;
    float invf = expf(-(float)j * 0.28782313662425572f);
    float ph = p * invf;
    float out = x * cosf(ph) + rh * sinf(ph);
    qout[(((size_t)(b * NH_ + h)) * LQ_ + t) * HD_ + d] = out;
}

__global__ void rope_kv_kernel(const float* __restrict__ tmpkv,
                               const float* __restrict__ posk,
                               const float* __restrict__ distk,
                               float* __restrict__ kout,
                               float* __restrict__ vout) {
    int idx = blockIdx.x * blockDim.x + threadIdx.x;
    if (idx >= BB * LK_ * HID_) return;
    int d = idx & 63;
    int h = (idx >> 6) & 15;
    int t = (idx >> 10) & 2047;
    int b = idx >> 21;
    size_t rowbase = ((size_t)b * LK_ + t) * (2 * HID_);
    int hd = h * 64 + d;
    float x  = tmpkv[rowbase + hd];
    float xp = tmpkv[rowbase + (hd ^ 32)];
    float rh = (d < 32) ? -xp : xp;
    float p  = posk[b * LK_ + t];
    int j = d & 31;
    float invf = expf(-(float)j * 0.28782313662425572f);
    float ph = p * invf;
    int dj = (d < 32) ? d : d - 32;
    float fg = expf(-11.512925464970229f + (float)dj * 0.32666551948001156f);
    float dist = distk[b * LK_ + t];
    float arg = dist * fg;
    float demb = (d < 32) ? cosf(arg) : sinf(arg);
    float kr = x * cosf(ph) + rh * sinf(ph) + demb;
    size_t o = (((size_t)(b * NH_ + h)) * LK_ + t) * HD_ + d;
    kout[o] = kr;
    vout[o] = tmpkv[rowbase + HID_ + hd];
}

// ---------------- TF32 tensor-core flash attention ---------------------------
// CTA: 128 q rows, 8 warps (16 rows each, m16 fragments), K tiles of 64.
// Smem (tf32 bits): Qs[128][68], Ks[64][68], Vs[64][72], Ps[128][68], madd[64].
#define ALQ 68
#define ALV 72
__global__ __launch_bounds__(256) void attn_mma_kernel(
    const float* __restrict__ Qg, const float* __restrict__ Kg,
    const float* __restrict__ Vg, const int* __restrict__ validk,
    const int* __restrict__ validq, float* __restrict__ Og)
{
    extern __shared__ unsigned sh[];
    unsigned* Qs = sh;                    // 128*68
    unsigned* Ks = Qs + 128 * ALQ;        // 64*68
    unsigned* Vs = Ks + 64 * ALQ;         // 64*72
    unsigned* Ps = Vs + 64 * ALV;         // 128*68
    float* madd  = (float*)(Ps + 128 * ALQ); // 64

    const int qt = blockIdx.x, h = blockIdx.y, b = blockIdx.z;
    const int tid = threadIdx.x, lane = tid & 31, wid = tid >> 5;
    const int r = lane >> 2, c = lane & 3;

    const float* Qb = Qg + (((size_t)(b * NH_ + h)) * LQ_ + qt * 128) * HD_;
    const float* Kb = Kg + ((size_t)(b * NH_ + h)) * LK_ * HD_;
    const float* Vb = Vg + ((size_t)(b * NH_ + h)) * LK_ * HD_;

    // Q tile 128x64 -> smem (tf32, rna)
    #pragma unroll
    for (int j = 0; j < 8; ++j) {
        int idx = tid + j * 256;              // float4 index 0..2047
        int row = idx >> 4, d4 = (idx & 15) * 4;
        float4 q = *(const float4*)(Qb + row * 64 + d4);
        uint4 t; t.x = f2tf(q.x); t.y = f2tf(q.y); t.z = f2tf(q.z); t.w = f2tf(q.w);
        *(uint4*)&Qs[row * ALQ + d4] = t;
    }

    float O[8][4] = {};
    float mrow[2] = {-1e30f, -1e30f};
    float lrow[2] = {0.f, 0.f};

    float4 kreg[4], vreg[4];
    auto ldtile = [&](int kt) {
        const float* Kt = Kb + (size_t)kt * 64 * HD_;
        const float* Vt = Vb + (size_t)kt * 64 * HD_;
        #pragma unroll
        for (int j = 0; j < 4; ++j) {
            int idx = tid + j * 256;          // float4 index 0..1023
            int row = idx >> 4, d4 = (idx & 15) * 4;
            kreg[j] = *(const float4*)(Kt + row * 64 + d4);
            vreg[j] = *(const float4*)(Vt + row * 64 + d4);
        }
    };
    auto sttile = [&](int kt) {
        #pragma unroll
        for (int j = 0; j < 4; ++j) {
            int idx = tid + j * 256;
            int row = idx >> 4, d4 = (idx & 15) * 4;
            uint4 tk; tk.x = f2tf(kreg[j].x); tk.y = f2tf(kreg[j].y);
                      tk.z = f2tf(kreg[j].z); tk.w = f2tf(kreg[j].w);
            *(uint4*)&Ks[row * ALQ + d4] = tk;
            uint4 tv; tv.x = f2tf(vreg[j].x); tv.y = f2tf(vreg[j].y);
                      tv.z = f2tf(vreg[j].z); tv.w = f2tf(vreg[j].w);
            *(uint4*)&Vs[row * ALV + d4] = tv;
        }
        if (tid < 64)
            madd[tid] = validk[b * LK_ + kt * 64 + tid] ? 0.0f : -1e9f;
    };

    ldtile(0);
    sttile(0);
    __syncthreads();

    const int NKT = LK_ / 64;
    for (int kt = 0; kt < NKT; ++kt) {
        if (kt + 1 < NKT) ldtile(kt + 1);

        // ---- S = Q K^T ----
        float S[8][4] = {};
        #pragma unroll
        for (int ks = 0; ks < 8; ++ks) {
            unsigned a[4];
            int ab = (wid * 16 + r) * ALQ + ks * 8 + c;
            a[0] = Qs[ab]; a[1] = Qs[ab + 8 * ALQ]; a[2] = Qs[ab + 4]; a[3] = Qs[ab + 8 * ALQ + 4];
            #pragma unroll
            for (int nt = 0; nt < 8; ++nt) {
                unsigned bf[2];
                int nb = (nt * 8 + r) * ALQ + ks * 8 + c;
                bf[0] = Ks[nb]; bf[1] = Ks[nb + 4];
                mma8(S[nt], a, bf);
            }
        }

        // ---- mask + online softmax (register, FA2-style) ----
        float m0 = mrow[0], m1 = mrow[1];
        #pragma unroll
        for (int nt = 0; nt < 8; ++nt) {
            float2 mv = *(const float2*)&madd[nt * 8 + 2 * c];
            S[nt][0] += mv.x; S[nt][1] += mv.y;
            S[nt][2] += mv.x; S[nt][3] += mv.y;
            m0 = fmaxf(m0, fmaxf(S[nt][0], S[nt][1]));
            m1 = fmaxf(m1, fmaxf(S[nt][2], S[nt][3]));
        }
        m0 = fmaxf(m0, __shfl_xor_sync(0xffffffffu, m0, 1));
        m0 = fmaxf(m0, __shfl_xor_sync(0xffffffffu, m0, 2));
        m1 = fmaxf(m1, __shfl_xor_sync(0xffffffffu, m1, 1));
        m1 = fmaxf(m1, __shfl_xor_sync(0xffffffffu, m1, 2));
        float a0 = __expf(mrow[0] - m0), a1 = __expf(mrow[1] - m1);
        mrow[0] = m0; mrow[1] = m1;

        float ls0 = 0.f, ls1 = 0.f;
        #pragma unroll
        for (int nt = 0; nt < 8; ++nt) {
            S[nt][0] = __expf(S[nt][0] - m0);
            S[nt][1] = __expf(S[nt][1] - m0);
            S[nt][2] = __expf(S[nt][2] - m1);
            S[nt][3] = __expf(S[nt][3] - m1);
            ls0 += S[nt][0] + S[nt][1];
            ls1 += S[nt][2] + S[nt][3];
            int pb = (wid * 16 + r) * ALQ + nt * 8 + 2 * c;
            uint2 p0; p0.x = f2tf(S[nt][0]); p0.y = f2tf(S[nt][1]);
            *(uint2*)&Ps[pb] = p0;
            uint2 p1; p1.x = f2tf(S[nt][2]); p1.y = f2tf(S[nt][3]);
            *(uint2*)&Ps[pb + 8 * ALQ] = p1;
        }
        ls0 += __shfl_xor_sync(0xffffffffu, ls0, 1);
        ls0 += __shfl_xor_sync(0xffffffffu, ls0, 2);
        ls1 += __shfl_xor_sync(0xffffffffu, ls1, 1);
        ls1 += __shfl_xor_sync(0xffffffffu, ls1, 2);
        lrow[0] = lrow[0] * a0 + ls0;
        lrow[1] = lrow[1] * a1 + ls1;

        #pragma unroll
        for (int nt = 0; nt < 8; ++nt) {
            O[nt][0] *= a0; O[nt][1] *= a0; O[nt][2] *= a1; O[nt][3] *= a1;
        }
        __syncwarp();

        // ---- O += P V ----
        #pragma unroll
        for (int ks = 0; ks < 8; ++ks) {
            unsigned a[4];
            int ab = (wid * 16 + r) * ALQ + ks * 8 + c;
            a[0] = Ps[ab]; a[1] = Ps[ab + 8 * ALQ]; a[2] = Ps[ab + 4]; a[3] = Ps[ab + 8 * ALQ + 4];
            #pragma unroll
            for (int nt = 0; nt < 8; ++nt) {
                unsigned bf[2];
                int vb = (ks * 8 + c) * ALV + nt * 8 + r;
                bf[0] = Vs[vb]; bf[1] = Vs[vb + 4 * ALV];
                mma8(O[nt], a, bf);
            }
        }
        __syncthreads();
        if (kt + 1 < NKT) { sttile(kt + 1); __syncthreads(); }
    }

    // ---- epilogue ----
    int row0 = qt * 128 + wid * 16 + r;
    int vq0 = validq[b * LQ_ + row0];
    int vq1 = validq[b * LQ_ + row0 + 8];
    float inv0 = vq0 ? 1.0f / lrow[0] : 0.0f;
    float inv1 = vq1 ? 1.0f / lrow[1] : 0.0f;
    float* Ob0 = Og + ((size_t)b * LQ_ + row0) * HID_ + h * 64;
    float* Ob1 = Ob0 + 8 * HID_;
    #pragma unroll
    for (int nt = 0; nt < 8; ++nt) {
        int cc = nt * 8 + 2 * c;
        float2 o0; o0.x = O[nt][0] * inv0; o0.y = O[nt][1] * inv0;
        *(float2*)&Ob0[cc] = o0;
        float2 o1; o1.x = O[nt][2] * inv1; o1.y = O[nt][3] * inv1;
        *(float2*)&Ob1[cc] = o1;
    }
}

// ---------------- launch -----------------------------------------------------
extern "C" void kernel_launch(void* const* d_in, const int* in_sizes, int n_in,
                              void* d_out, int out_size) {
    const float* q_states  = (const float*)d_in[0];
    const float* kv_states = (const float*)d_in[1];
    const float* distances = (const float*)d_in[2];
    const int*   mask_q    = (const int*)d_in[3];
    const int*   mask_kv   = (const int*)d_in[4];
    const float* Wq        = (const float*)d_in[5];
    const float* bq        = (const float*)d_in[6];
    const float* Wkv       = (const float*)d_in[7];
    const float* bkv       = (const float*)d_in[8];
    const float* Wo        = (const float*)d_in[9];
    const float* bo        = (const float*)d_in[10];
    float* out = (float*)d_out;

    float *p_tmpq, *p_tmpkv, *p_q, *p_k, *p_v, *p_att, *p_posq, *p_posk, *p_distk;
    int *p_boundq, *p_boundk, *p_validq, *p_validk;
    cudaGetSymbolAddress((void**)&p_tmpq,  g_tmpq);
    cudaGetSymbolAddress((void**)&p_tmpkv, g_tmpkv);
    cudaGetSymbolAddress((void**)&p_q,     g_q);
    cudaGetSymbolAddress((void**)&p_k,     g_k);
    cudaGetSymbolAddress((void**)&p_v,     g_v);
    cudaGetSymbolAddress((void**)&p_att,   g_att);
    cudaGetSymbolAddress((void**)&p_posq,  g_posq);
    cudaGetSymbolAddress((void**)&p_posk,  g_posk);
    cudaGetSymbolAddress((void**)&p_distk, g_distk);
    cudaGetSymbolAddress((void**)&p_boundq, g_boundq);
    cudaGetSymbolAddress((void**)&p_boundk, g_boundk);
    cudaGetSymbolAddress((void**)&p_validq, g_validq);
    cudaGetSymbolAddress((void**)&p_validk, g_validk);

    cumsum_kernel<<<BB, 1024>>>(mask_q,  p_boundq, LQ_);
    cumsum_kernel<<<BB, 1024>>>(mask_kv, p_boundk, LK_);
    posval_kernel<<<(BB * LQ_ + 255) / 256, 256>>>(mask_q,  p_boundq, nullptr,   p_posq, p_validq, nullptr, LQ_);
    posval_kernel<<<(BB * LK_ + 255) / 256, 256>>>(mask_kv, p_boundk, distances, p_posk, p_validk, p_distk, LK_);

    // projections (TF32 tensor cores)
    dim3 gq(HID_ / 128, BB * LQ_ / 128);
    tgemm_kernel<<<gq, 256>>>(q_states, Wq, bq, p_tmpq, BB * LQ_, HID_, HID_, 0.125f);
    dim3 gkv(2 * HID_ / 128, BB * LK_ / 128);
    tgemm_kernel<<<gkv, 256>>>(kv_states, Wkv, bkv, p_tmpkv, BB * LK_, 2 * HID_, HID_, 1.0f);

    rope_q_kernel <<<BB * LQ_ * HID_ / 256, 256>>>(p_tmpq, p_posq, p_q);
    rope_kv_kernel<<<BB * LK_ * HID_ / 256, 256>>>(p_tmpkv, p_posk, p_distk, p_k, p_v);

    // attention (TF32 tensor cores, FA2)
    size_t smem = (size_t)(128 * ALQ + 64 * ALQ + 64 * ALV + 128 * ALQ) * 4 + 64 * 4;
    cudaFuncSetAttribute(attn_mma_kernel, cudaFuncAttributeMaxDynamicSharedMemorySize, (int)smem);
    attn_mma_kernel<<<dim3(LQ_ / 128, NH_, BB), 256, smem>>>(p_q, p_k, p_v, p_validk, p_validq, p_att);

    // output projection
    tgemm_kernel<<<gq, 256>>>(p_att, Wo, bo, out, BB * LQ_, HID_, HID_, 1.0f);
}

// round 3
// speedup vs baseline: 3.0998x; 1.7069x over previous
#include <cuda_runtime.h>
#include <math.h>

#define BB   2
#define LQ_  2048
#define LK_  2048
#define HID_ 1024
#define NH_  16
#define HD_  64
#define NKT  (LK_/64)

// ---------------- scratch ----------------------------------------------------
__device__ float g_tmpq [BB*LQ_*HID_];
__device__ float g_tmpkv[BB*LK_*2*HID_];
__device__ float g_q [BB*NH_*LQ_*HD_];
__device__ float g_k [BB*NH_*LK_*HD_];
__device__ float g_v [BB*NH_*LK_*HD_];
__device__ float g_att[BB*LQ_*HID_];
__device__ float g_aq [BB*LQ_*HID_];     // tf32 copies of inputs/weights
__device__ float g_akv[BB*LK_*HID_];
__device__ float g_wq [HID_*HID_];
__device__ float g_wkv[HID_*2*HID_];
__device__ float g_wo [HID_*HID_];
__device__ int   g_boundq[BB*LQ_];
__device__ int   g_boundk[BB*LK_];
__device__ float g_posq[BB*LQ_];
__device__ float g_posk[BB*LK_];
__device__ float g_distk[BB*LK_];
__device__ int   g_validq[BB*LQ_];
__device__ int   g_validk[BB*LK_];

// ---------------- helpers ----------------------------------------------------
__device__ __forceinline__ unsigned f2tf(float x) {
    unsigned r;
    asm("cvt.rna.tf32.f32 %0, %1;" : "=r"(r) : "f"(x));
    return r;
}

__device__ __forceinline__ void mma8(float* c, const unsigned* a, const unsigned* b) {
    asm volatile(
        "mma.sync.aligned.m16n8k8.row.col.f32.tf32.tf32.f32 "
        "{%0,%1,%2,%3}, {%4,%5,%6,%7}, {%8,%9}, {%0,%1,%2,%3};"
        : "+f"(c[0]), "+f"(c[1]), "+f"(c[2]), "+f"(c[3])
        : "r"(a[0]), "r"(a[1]), "r"(a[2]), "r"(a[3]), "r"(b[0]), "r"(b[1]));
}

__device__ __forceinline__ void cpa16(void* sdst, const void* gsrc) {
    unsigned sa = (unsigned)__cvta_generic_to_shared(sdst);
    asm volatile("cp.async.cg.shared.global [%0], [%1], 16;" :: "r"(sa), "l"(gsrc));
}
#define CPA_COMMIT() asm volatile("cp.async.commit_group;" ::: "memory")
#define CPA_WAIT1()  asm volatile("cp.async.wait_group 1;" ::: "memory")
#define CPA_WAIT0()  asm volatile("cp.async.wait_group 0;" ::: "memory")

// ---------------- segment geometry ------------------------------------------
__global__ void cumsum_kernel(const int* __restrict__ mask, int* __restrict__ bound, int L) {
    __shared__ int s[LK_];
    int b = blockIdx.x;
    for (int i = threadIdx.x; i < L; i += blockDim.x) s[i] = mask[b * L + i];
    __syncthreads();
    for (int i = threadIdx.x; i < L; i += blockDim.x) {
        int acc = 0;
        for (int j = 0; j <= i; ++j) acc += s[j];
        bound[b * L + i] = acc;
    }
}

__global__ void posval_kernel(const int* __restrict__ mask, const int* __restrict__ bound,
                              const float* __restrict__ distances,
                              float* __restrict__ pos, int* __restrict__ valid,
                              float* __restrict__ dist, int L) {
    int idx = blockIdx.x * blockDim.x + threadIdx.x;
    if (idx >= BB * L) return;
    int b = idx / L, t = idx - b * L;
    const int* bo = bound + b * L;
    int lo = 0, hi = L;
    while (lo < hi) { int mid = (lo + hi) >> 1; if (bo[mid] <= t) lo = mid + 1; else hi = mid; }
    int seg = lo < (L - 1) ? lo : (L - 1);
    int v = (t < bo[L - 1]) ? 1 : 0;
    int start = bo[seg] - mask[b * L + seg];
    pos[idx] = v ? (float)(t - start) : 0.0f;
    valid[idx] = v;
    if (dist) dist[idx] = v ? distances[b * L + seg] : 0.0f;
}

// ---------------- tf32 pre-conversion ----------------------------------------
__global__ void cvt_tf32_kernel(const float* __restrict__ in, float* __restrict__ out, int n4) {
    int i = blockIdx.x * blockDim.x + threadIdx.x;
    if (i >= n4) return;
    float4 v = ((const float4*)in)[i];
    uint4 t; t.x = f2tf(v.x); t.y = f2tf(v.y); t.z = f2tf(v.z); t.w = f2tf(v.w);
    ((uint4*)out)[i] = t;
}

// ---------------- TF32 GEMM, cp.async double-buffered ------------------------
// A: MxK row-major (tf32 bits), B: KxN row-major (tf32 bits). CTA 128x128, k-chunk 16.
#define GLDA 20
#define GLDB 136
__global__ __launch_bounds__(256) void tgemm_kernel(
    const float* __restrict__ A, const float* __restrict__ Bm,
    const float* __restrict__ bias, float* __restrict__ C,
    int M, int N, int K, float scale)
{
    __shared__ unsigned Asb[2][128 * GLDA];
    __shared__ unsigned Bsb[2][16 * GLDB];
    const int tid = threadIdx.x, lane = tid & 31, wid = tid >> 5;
    const int wm = wid >> 2, wn = wid & 3;
    const int r = lane >> 2, c = lane & 3;
    const int bm = blockIdx.y * 128, bn = blockIdx.x * 128;
    const float* Ag = A + (size_t)bm * K;

    float acc[4][4][4] = {};

    auto issue = [&](int kc, int buf) {
        #pragma unroll
        for (int j = 0; j < 2; ++j) {
            int idx = tid + j * 256;
            int row = idx >> 2, kq = (idx & 3) * 4;
            cpa16(&Asb[buf][row * GLDA + kq], Ag + (size_t)row * K + kc * 16 + kq);
        }
        #pragma unroll
        for (int j = 0; j < 2; ++j) {
            int idx = tid + j * 256;
            int kk = idx >> 5, n4 = (idx & 31) * 4;
            cpa16(&Bsb[buf][kk * GLDB + n4], Bm + (size_t)(kc * 16 + kk) * N + bn + n4);
        }
    };

    issue(0, 0);
    CPA_COMMIT();

    const int NKC = K / 16;
    for (int kc = 0; kc < NKC; ++kc) {
        int buf = kc & 1;
        __syncthreads();                      // all warps done reading buf^1
        if (kc + 1 < NKC) {
            issue(kc + 1, buf ^ 1);
            CPA_COMMIT();
            CPA_WAIT1();
        } else {
            CPA_WAIT0();
        }
        __syncthreads();                      // data for this tile visible

        const unsigned* As = Asb[buf];
        const unsigned* Bs = Bsb[buf];
        #pragma unroll
        for (int ks = 0; ks < 2; ++ks) {
            unsigned af[4][4], bf[4][2];
            #pragma unroll
            for (int mt = 0; mt < 4; ++mt) {
                int base = (wm * 64 + mt * 16 + r) * GLDA + ks * 8 + c;
                af[mt][0] = As[base];
                af[mt][1] = As[base + 8 * GLDA];
                af[mt][2] = As[base + 4];
                af[mt][3] = As[base + 8 * GLDA + 4];
            }
            #pragma unroll
            for (int nt = 0; nt < 4; ++nt) {
                int n0 = wn * 32 + nt * 8 + r;
                int kc2 = ks * 8 + c;
                bf[nt][0] = Bs[kc2 * GLDB + n0];
                bf[nt][1] = Bs[(kc2 + 4) * GLDB + n0];
            }
            #pragma unroll
            for (int mt = 0; mt < 4; ++mt)
                #pragma unroll
                for (int nt = 0; nt < 4; ++nt)
                    mma8(acc[mt][nt], af[mt], bf[nt]);
        }
    }

    #pragma unroll
    for (int mt = 0; mt < 4; ++mt) {
        #pragma unroll
        for (int nt = 0; nt < 4; ++nt) {
            int row = bm + wm * 64 + mt * 16 + r;
            int cc  = bn + wn * 32 + nt * 8 + 2 * c;
            float b0 = bias[cc], b1 = bias[cc + 1];
            C[(size_t)row * N + cc]           = (acc[mt][nt][0] + b0) * scale;
            C[(size_t)row * N + cc + 1]       = (acc[mt][nt][1] + b1) * scale;
            C[(size_t)(row + 8) * N + cc]     = (acc[mt][nt][2] + b0) * scale;
            C[(size_t)(row + 8) * N + cc + 1] = (acc[mt][nt][3] + b1) * scale;
        }
    }
}

// ---------------- RoPE kernels (emit tf32-rounded values) ---------------------
__global__ void rope_q_kernel(const float* __restrict__ tmpq,
                              const float* __restrict__ posq,
                              float* __restrict__ qout) {
    int idx = blockIdx.x * blockDim.x + threadIdx.x;
    if (idx >= BB * LQ_ * HID_) return;
    int d = idx & 63;
    int h = (idx >> 6) & 15;
    int t = (idx >> 10) & 2047;
    int b = idx >> 21;
    float x  = tmpq[idx];
    float xp = tmpq[idx ^ 32];
    float rh = (d < 32) ? -xp : xp;
    float p  = posq[b * LQ_ + t];
    int j = d & 31;
    float invf = expf(-(float)j * 0.28782313662425572f);
    float ph = p * invf;
    float out = x * cosf(ph) + rh * sinf(ph);
    qout[(((size_t)(b * NH_ + h)) * LQ_ + t) * HD_ + d] = __uint_as_float(f2tf(out));
}

__global__ void rope_kv_kernel(const float* __restrict__ tmpkv,
                               const float* __restrict__ posk,
                               const float* __restrict__ distk,
                               float* __restrict__ kout,
                               float* __restrict__ vout) {
    int idx = blockIdx.x * blockDim.x + threadIdx.x;
    if (idx >= BB * LK_ * HID_) return;
    int d = idx & 63;
    int h = (idx >> 6) & 15;
    int t = (idx >> 10) & 2047;
    int b = idx >> 21;
    size_t rowbase = ((size_t)b * LK_ + t) * (2 * HID_);
    int hd = h * 64 + d;
    float x  = tmpkv[rowbase + hd];
    float xp = tmpkv[rowbase + (hd ^ 32)];
    float rh = (d < 32) ? -xp : xp;
    float p  = posk[b * LK_ + t];
    int j = d & 31;
    float invf = expf(-(float)j * 0.28782313662425572f);
    float ph = p * invf;
    int dj = (d < 32) ? d : d - 32;
    float fg = expf(-11.512925464970229f + (float)dj * 0.32666551948001156f);
    float dist = distk[b * LK_ + t];
    float arg = dist * fg;
    float demb = (d < 32) ? cosf(arg) : sinf(arg);
    float kr = x * cosf(ph) + rh * sinf(ph) + demb;
    size_t o = (((size_t)(b * NH_ + h)) * LK_ + t) * HD_ + d;
    kout[o] = __uint_as_float(f2tf(kr));
    vout[o] = __uint_as_float(f2tf(tmpkv[rowbase + HID_ + hd]));
}

// ---------------- TF32 flash attention, cp.async + shfl P-convert ------------
// CTA: 128 q rows, 8 warps (16 rows each). K tiles of 64, double buffered.
#define ALQ 68
#define ALV 72
__global__ __launch_bounds__(256) void attn_mma_kernel(
    const float* __restrict__ Qg, const float* __restrict__ Kg,
    const float* __restrict__ Vg, const int* __restrict__ validk,
    const int* __restrict__ validq, float* __restrict__ Og)
{
    extern __shared__ unsigned sh[];
    unsigned* Qs   = sh;                         // 128*68
    unsigned* Ksb  = Qs + 128 * ALQ;             // 2 * 64*68
    unsigned* Vsb  = Ksb + 2 * 64 * ALQ;         // 2 * 64*72
    float*    madb = (float*)(Vsb + 2 * 64 * ALV); // 2 * 64

    const int qt = blockIdx.x, h = blockIdx.y, b = blockIdx.z;
    const int tid = threadIdx.x, lane = tid & 31, wid = tid >> 5;
    const int r = lane >> 2, c = lane & 3;

    const float* Qb = Qg + (((size_t)(b * NH_ + h)) * LQ_ + qt * 128) * HD_;
    const float* Kb = Kg + ((size_t)(b * NH_ + h)) * LK_ * HD_;
    const float* Vb = Vg + ((size_t)(b * NH_ + h)) * LK_ * HD_;

    auto issue_tile = [&](int kt, int buf) {
        const float* Kt = Kb + (size_t)kt * 64 * HD_;
        const float* Vt = Vb + (size_t)kt * 64 * HD_;
        unsigned* Kd = Ksb + buf * 64 * ALQ;
        unsigned* Vd = Vsb + buf * 64 * ALV;
        #pragma unroll
        for (int j = 0; j < 4; ++j) {
            int idx = tid + j * 256;
            int row = idx >> 4, d4 = (idx & 15) * 4;
            cpa16(Kd + row * ALQ + d4, Kt + row * 64 + d4);
            cpa16(Vd + row * ALV + d4, Vt + row * 64 + d4);
        }
        if (tid < 64)
            madb[buf * 64 + tid] = validk[b * LK_ + kt * 64 + tid] ? 0.0f : -1e9f;
    };

    // prologue: Q tile + K/V tile 0 in one async group
    #pragma unroll
    for (int j = 0; j < 8; ++j) {
        int idx = tid + j * 256;
        int row = idx >> 4, d4 = (idx & 15) * 4;
        cpa16(Qs + row * ALQ + d4, Qb + row * 64 + d4);
    }
    issue_tile(0, 0);
    CPA_COMMIT();

    float O[8][4] = {};
    float mrow[2] = {-1e30f, -1e30f};
    float lrow[2] = {0.f, 0.f};

    for (int kt = 0; kt < NKT; ++kt) {
        int buf = kt & 1;
        __syncthreads();                       // all warps done reading buf^1
        if (kt + 1 < NKT) {
            issue_tile(kt + 1, buf ^ 1);
            CPA_COMMIT();
            CPA_WAIT1();
        } else {
            CPA_WAIT0();
        }
        __syncthreads();                       // tile kt (+ madd) visible

        const unsigned* Ks = Ksb + buf * 64 * ALQ;
        const unsigned* Vs = Vsb + buf * 64 * ALV;
        const float* madd = madb + buf * 64;

        // ---- S = Q K^T ----
        float S[8][4] = {};
        #pragma unroll
        for (int ks = 0; ks < 8; ++ks) {
            unsigned a[4];
            int ab = (wid * 16 + r) * ALQ + ks * 8 + c;
            a[0] = Qs[ab]; a[1] = Qs[ab + 8 * ALQ]; a[2] = Qs[ab + 4]; a[3] = Qs[ab + 8 * ALQ + 4];
            #pragma unroll
            for (int nt = 0; nt < 8; ++nt) {
                unsigned bf[2];
                int nb = (nt * 8 + r) * ALQ + ks * 8 + c;
                bf[0] = Ks[nb]; bf[1] = Ks[nb + 4];
                mma8(S[nt], a, bf);
            }
        }

        // ---- mask + online softmax ----
        float m0 = mrow[0], m1 = mrow[1];
        #pragma unroll
        for (int nt = 0; nt < 8; ++nt) {
            float2 mv = *(const float2*)&madd[nt * 8 + 2 * c];
            S[nt][0] += mv.x; S[nt][1] += mv.y;
            S[nt][2] += mv.x; S[nt][3] += mv.y;
            m0 = fmaxf(m0, fmaxf(S[nt][0], S[nt][1]));
            m1 = fmaxf(m1, fmaxf(S[nt][2], S[nt][3]));
        }
        m0 = fmaxf(m0, __shfl_xor_sync(0xffffffffu, m0, 1));
        m0 = fmaxf(m0, __shfl_xor_sync(0xffffffffu, m0, 2));
        m1 = fmaxf(m1, __shfl_xor_sync(0xffffffffu, m1, 1));
        m1 = fmaxf(m1, __shfl_xor_sync(0xffffffffu, m1, 2));
        float a0 = __expf(mrow[0] - m0), a1 = __expf(mrow[1] - m1);
        mrow[0] = m0; mrow[1] = m1;

        float ls0 = 0.f, ls1 = 0.f;
        #pragma unroll
        for (int nt = 0; nt < 8; ++nt) {
            S[nt][0] = __expf(S[nt][0] - m0);
            S[nt][1] = __expf(S[nt][1] - m0);
            S[nt][2] = __expf(S[nt][2] - m1);
            S[nt][3] = __expf(S[nt][3] - m1);
            ls0 += S[nt][0] + S[nt][1];
            ls1 += S[nt][2] + S[nt][3];
        }
        ls0 += __shfl_xor_sync(0xffffffffu, ls0, 1);
        ls0 += __shfl_xor_sync(0xffffffffu, ls0, 2);
        ls1 += __shfl_xor_sync(0xffffffffu, ls1, 1);
        ls1 += __shfl_xor_sync(0xffffffffu, ls1, 2);
        lrow[0] = lrow[0] * a0 + ls0;
        lrow[1] = lrow[1] * a1 + ls1;

        #pragma unroll
        for (int nt = 0; nt < 8; ++nt) {
            O[nt][0] *= a0; O[nt][1] *= a0; O[nt][2] *= a1; O[nt][3] *= a1;
        }

        // ---- O += P V : convert C-frag -> A-frag in-register via shfl ----
        const int src0 = r * 4 + (c >> 1);
        const int src1 = src0 + 2;
        const int sel  = c & 1;
        #pragma unroll
        for (int ks = 0; ks < 8; ++ks) {
            float v00 = __shfl_sync(0xffffffffu, S[ks][0], src0);
            float v01 = __shfl_sync(0xffffffffu, S[ks][1], src0);
            float v20 = __shfl_sync(0xffffffffu, S[ks][2], src0);
            float v21 = __shfl_sync(0xffffffffu, S[ks][3], src0);
            float w00 = __shfl_sync(0xffffffffu, S[ks][0], src1);
            float w01 = __shfl_sync(0xffffffffu, S[ks][1], src1);
            float w20 = __shfl_sync(0xffffffffu, S[ks][2], src1);
            float w21 = __shfl_sync(0xffffffffu, S[ks][3], src1);
            unsigned a[4];
            a[0] = f2tf(sel ? v01 : v00);
            a[1] = f2tf(sel ? v21 : v20);
            a[2] = f2tf(sel ? w01 : w00);
            a[3] = f2tf(sel ? w21 : w20);
            #pragma unroll
            for (int nt = 0; nt < 8; ++nt) {
                unsigned bf[2];
                int vb = (ks * 8 + c) * ALV + nt * 8 + r;
                bf[0] = Vs[vb]; bf[1] = Vs[vb + 4 * ALV];
                mma8(O[nt], a, bf);
            }
        }
    }

    // ---- epilogue: tf32-rounded output (feeds Oproj directly) ----
    int row0 = qt * 128 + wid * 16 + r;
    int vq0 = validq[b * LQ_ + row0];
    int vq1 = validq[b * LQ_ + row0 + 8];
    float inv0 = vq0 ? 1.0f / lrow[0] : 0.0f;
    float inv1 = vq1 ? 1.0f / lrow[1] : 0.0f;
    float* Ob0 = Og + ((size_t)b * LQ_ + row0) * HID_ + h * 64;
    float* Ob1 = Ob0 + 8 * HID_;
    #pragma unroll
    for (int nt = 0; nt < 8; ++nt) {
        int cc = nt * 8 + 2 * c;
        float2 o0;
        o0.x = __uint_as_float(f2tf(O[nt][0] * inv0));
        o0.y = __uint_as_float(f2tf(O[nt][1] * inv0));
        *(float2*)&Ob0[cc] = o0;
        float2 o1;
        o1.x = __uint_as_float(f2tf(O[nt][2] * inv1));
        o1.y = __uint_as_float(f2tf(O[nt][3] * inv1));
        *(float2*)&Ob1[cc] = o1;
    }
}

// ---------------- launch -----------------------------------------------------
extern "C" void kernel_launch(void* const* d_in, const int* in_sizes, int n_in,
                              void* d_out, int out_size) {
    const float* q_states  = (const float*)d_in[0];
    const float* kv_states = (const float*)d_in[1];
    const float* distances = (const float*)d_in[2];
    const int*   mask_q    = (const int*)d_in[3];
    const int*   mask_kv   = (const int*)d_in[4];
    const float* Wq        = (const float*)d_in[5];
    const float* bq        = (const float*)d_in[6];
    const float* Wkv       = (const float*)d_in[7];
    const float* bkv       = (const float*)d_in[8];
    const float* Wo        = (const float*)d_in[9];
    const float* bo        = (const float*)d_in[10];
    float* out = (float*)d_out;

    float *p_tmpq, *p_tmpkv, *p_q, *p_k, *p_v, *p_att, *p_posq, *p_posk, *p_distk;
    float *p_aq, *p_akv, *p_wq, *p_wkv, *p_wo;
    int *p_boundq, *p_boundk, *p_validq, *p_validk;
    cudaGetSymbolAddress((void**)&p_tmpq,  g_tmpq);
    cudaGetSymbolAddress((void**)&p_tmpkv, g_tmpkv);
    cudaGetSymbolAddress((void**)&p_q,     g_q);
    cudaGetSymbolAddress((void**)&p_k,     g_k);
    cudaGetSymbolAddress((void**)&p_v,     g_v);
    cudaGetSymbolAddress((void**)&p_att,   g_att);
    cudaGetSymbolAddress((void**)&p_aq,    g_aq);
    cudaGetSymbolAddress((void**)&p_akv,   g_akv);
    cudaGetSymbolAddress((void**)&p_wq,    g_wq);
    cudaGetSymbolAddress((void**)&p_wkv,   g_wkv);
    cudaGetSymbolAddress((void**)&p_wo,    g_wo);
    cudaGetSymbolAddress((void**)&p_posq,  g_posq);
    cudaGetSymbolAddress((void**)&p_posk,  g_posk);
    cudaGetSymbolAddress((void**)&p_distk, g_distk);
    cudaGetSymbolAddress((void**)&p_boundq, g_boundq);
    cudaGetSymbolAddress((void**)&p_boundk, g_boundk);
    cudaGetSymbolAddress((void**)&p_validq, g_validq);
    cudaGetSymbolAddress((void**)&p_validk, g_validk);

    cumsum_kernel<<<BB, 1024>>>(mask_q,  p_boundq, LQ_);
    cumsum_kernel<<<BB, 1024>>>(mask_kv, p_boundk, LK_);
    posval_kernel<<<(BB * LQ_ + 255) / 256, 256>>>(mask_q,  p_boundq, nullptr,   p_posq, p_validq, nullptr, LQ_);
    posval_kernel<<<(BB * LK_ + 255) / 256, 256>>>(mask_kv, p_boundk, distances, p_posk, p_validk, p_distk, LK_);

    // pre-convert inputs + weights to tf32
    cvt_tf32_kernel<<<(BB*LQ_*HID_/4 + 255)/256, 256>>>(q_states,  p_aq,  BB*LQ_*HID_/4);
    cvt_tf32_kernel<<<(BB*LK_*HID_/4 + 255)/256, 256>>>(kv_states, p_akv, BB*LK_*HID_/4);
    cvt_tf32_kernel<<<(HID_*HID_/4 + 255)/256, 256>>>(Wq,  p_wq,  HID_*HID_/4);
    cvt_tf32_kernel<<<(HID_*2*HID_/4 + 255)/256, 256>>>(Wkv, p_wkv, HID_*2*HID_/4);
    cvt_tf32_kernel<<<(HID_*HID_/4 + 255)/256, 256>>>(Wo,  p_wo,  HID_*HID_/4);

    // projections (TF32 tensor cores, async pipeline)
    dim3 gq(HID_ / 128, BB * LQ_ / 128);
    tgemm_kernel<<<gq, 256>>>(p_aq, p_wq, bq, p_tmpq, BB * LQ_, HID_, HID_, 0.125f);
    dim3 gkv(2 * HID_ / 128, BB * LK_ / 128);
    tgemm_kernel<<<gkv, 256>>>(p_akv, p_wkv, bkv, p_tmpkv, BB * LK_, 2 * HID_, HID_, 1.0f);

    rope_q_kernel <<<BB * LQ_ * HID_ / 256, 256>>>(p_tmpq, p_posq, p_q);
    rope_kv_kernel<<<BB * LK_ * HID_ / 256, 256>>>(p_tmpkv, p_posk, p_distk, p_k, p_v);

    // attention
    size_t smem = (size_t)(128 * ALQ + 2 * 64 * ALQ + 2 * 64 * ALV) * 4 + 2 * 64 * 4;
    cudaFuncSetAttribute(attn_mma_kernel, cudaFuncAttributeMaxDynamicSharedMemorySize, (int)smem);
    attn_mma_kernel<<<dim3(LQ_ / 128, NH_, BB), 256, smem>>>(p_q, p_k, p_v, p_validk, p_validq, p_att);

    // output projection (A already tf32 from attention epilogue)
    tgemm_kernel<<<gq, 256>>>(p_att, p_wo, bo, out, BB * LQ_, HID_, HID_, 1.0f);
}

// round 4
// speedup vs baseline: 5.4532x; 1.7592x over previous
#include <cuda_runtime.h>
#include <cuda_fp16.h>
#include <math.h>

#define BB   2
#define LQ_  2048
#define LK_  2048
#define HID_ 1024
#define NH_  16
#define HD_  64
#define NKT  (LK_/64)

// ---------------- scratch ----------------------------------------------------
__device__ float  g_tmpq [BB*LQ_*HID_];
__device__ float  g_tmpkv[BB*LK_*2*HID_];
__device__ __half g_qh [BB*NH_*LQ_*HD_];
__device__ __half g_kh [BB*NH_*LK_*HD_];
__device__ __half g_vh [BB*NH_*LK_*HD_];
__device__ __half g_atth[BB*LQ_*HID_];
__device__ __half g_aqh [BB*LQ_*HID_];
__device__ __half g_akvh[BB*LK_*HID_];
__device__ __half g_wqh [HID_*HID_];
__device__ __half g_wkvh[HID_*2*HID_];
__device__ __half g_woh [HID_*HID_];
__device__ int    g_boundq[BB*LQ_];
__device__ int    g_boundk[BB*LK_];
__device__ float  g_posq[BB*LQ_];
__device__ float  g_posk[BB*LK_];
__device__ float  g_distk[BB*LK_];
__device__ int    g_validq[BB*LQ_];
__device__ int    g_validk[BB*LK_];

// ---------------- helpers ----------------------------------------------------
__device__ __forceinline__ unsigned smem_u32(const void* p) {
    return (unsigned)__cvta_generic_to_shared(p);
}
__device__ __forceinline__ void ldsm_x4(unsigned& r0, unsigned& r1, unsigned& r2, unsigned& r3, unsigned a) {
    asm volatile("ldmatrix.sync.aligned.m8n8.x4.shared.b16 {%0,%1,%2,%3}, [%4];"
                 : "=r"(r0), "=r"(r1), "=r"(r2), "=r"(r3) : "r"(a));
}
__device__ __forceinline__ void ldsm_x4_t(unsigned& r0, unsigned& r1, unsigned& r2, unsigned& r3, unsigned a) {
    asm volatile("ldmatrix.sync.aligned.m8n8.x4.trans.shared.b16 {%0,%1,%2,%3}, [%4];"
                 : "=r"(r0), "=r"(r1), "=r"(r2), "=r"(r3) : "r"(a));
}
__device__ __forceinline__ void mma16(float* c, const unsigned* a, const unsigned* b) {
    asm volatile(
        "mma.sync.aligned.m16n8k16.row.col.f32.f16.f16.f32 "
        "{%0,%1,%2,%3}, {%4,%5,%6,%7}, {%8,%9}, {%0,%1,%2,%3};"
        : "+f"(c[0]), "+f"(c[1]), "+f"(c[2]), "+f"(c[3])
        : "r"(a[0]), "r"(a[1]), "r"(a[2]), "r"(a[3]), "r"(b[0]), "r"(b[1]));
}
__device__ __forceinline__ unsigned pack2h(float x, float y) {
    __half2 h = __floats2half2_rn(x, y);
    return *(unsigned*)&h;
}
__device__ __forceinline__ void cpa16(void* sdst, const void* gsrc) {
    unsigned sa = smem_u32(sdst);
    asm volatile("cp.async.cg.shared.global [%0], [%1], 16;" :: "r"(sa), "l"(gsrc));
}
#define CPA_COMMIT() asm volatile("cp.async.commit_group;" ::: "memory")
#define CPA_WAIT1()  asm volatile("cp.async.wait_group 1;" ::: "memory")
#define CPA_WAIT0()  asm volatile("cp.async.wait_group 0;" ::: "memory")

// ---------------- segment geometry ------------------------------------------
__global__ void cumsum_kernel(const int* __restrict__ mask, int* __restrict__ bound, int L) {
    __shared__ int s[LK_];
    int b = blockIdx.x;
    for (int i = threadIdx.x; i < L; i += blockDim.x) s[i] = mask[b * L + i];
    __syncthreads();
    for (int i = threadIdx.x; i < L; i += blockDim.x) {
        int acc = 0;
        for (int j = 0; j <= i; ++j) acc += s[j];
        bound[b * L + i] = acc;
    }
}

__global__ void posval_kernel(const int* __restrict__ mask, const int* __restrict__ bound,
                              const float* __restrict__ distances,
                              float* __restrict__ pos, int* __restrict__ valid,
                              float* __restrict__ dist, int L) {
    int idx = blockIdx.x * blockDim.x + threadIdx.x;
    if (idx >= BB * L) return;
    int b = idx / L, t = idx - b * L;
    const int* bo = bound + b * L;
    int lo = 0, hi = L;
    while (lo < hi) { int mid = (lo + hi) >> 1; if (bo[mid] <= t) lo = mid + 1; else hi = mid; }
    int seg = lo < (L - 1) ? lo : (L - 1);
    int v = (t < bo[L - 1]) ? 1 : 0;
    int start = bo[seg] - mask[b * L + seg];
    pos[idx] = v ? (float)(t - start) : 0.0f;
    valid[idx] = v;
    if (dist) dist[idx] = v ? distances[b * L + seg] : 0.0f;
}

// ---------------- f32 -> f16 conversion ---------------------------------------
__global__ void cvt_h_kernel(const float* __restrict__ in, __half* __restrict__ out, int n4) {
    int i = blockIdx.x * blockDim.x + threadIdx.x;
    if (i >= n4) return;
    float4 v = ((const float4*)in)[i];
    ((__half2*)out)[i * 2]     = __floats2half2_rn(v.x, v.y);
    ((__half2*)out)[i * 2 + 1] = __floats2half2_rn(v.z, v.w);
}

// ---------------- FP16 tensor GEMM: C = (A@B + bias)*scale -------------------
// A: MxK row-major half, B: KxN row-major half. CTA 128x128, k-chunk 32.
// As rows padded to 40 halves (80B), Bs rows to 136 halves (272B).
__global__ __launch_bounds__(256) void hgemm_kernel(
    const __half* __restrict__ A, const __half* __restrict__ Bm,
    const float* __restrict__ bias, float* __restrict__ C,
    int M, int N, int K, float scale)
{
    __shared__ __half Asb[2][128 * 40];
    __shared__ __half Bsb[2][32 * 136];
    const int tid = threadIdx.x, lane = tid & 31, wid = tid >> 5;
    const int wm = wid >> 2, wn = wid & 3;
    const int r = lane >> 2, c = lane & 3;
    const int quad = lane >> 3, lrow = lane & 7;
    const int bm = blockIdx.y * 128, bn = blockIdx.x * 128;
    const __half* Ag = A + (size_t)bm * K;

    float acc[4][4][4] = {};

    auto issue = [&](int kc, int buf) {
        #pragma unroll
        for (int j = 0; j < 2; ++j) {
            int idx = tid + j * 256;                 // 512 A chunks
            int row = idx >> 2, c16 = idx & 3;
            cpa16(&Asb[buf][row * 40 + c16 * 8], Ag + (size_t)row * K + kc * 32 + c16 * 8);
        }
        #pragma unroll
        for (int j = 0; j < 2; ++j) {
            int idx = tid + j * 256;                 // 512 B chunks
            int kk = idx >> 4, c16 = idx & 15;
            cpa16(&Bsb[buf][kk * 136 + c16 * 8], Bm + (size_t)(kc * 32 + kk) * N + bn + c16 * 8);
        }
    };

    issue(0, 0);
    CPA_COMMIT();

    const int NKC = K / 32;
    for (int kc = 0; kc < NKC; ++kc) {
        int buf = kc & 1;
        __syncthreads();
        if (kc + 1 < NKC) { issue(kc + 1, buf ^ 1); CPA_COMMIT(); CPA_WAIT1(); }
        else             { CPA_WAIT0(); }
        __syncthreads();

        const __half* As = Asb[buf];
        const __half* Bs = Bsb[buf];
        #pragma unroll
        for (int ks = 0; ks < 2; ++ks) {
            unsigned af[4][4];
            #pragma unroll
            for (int mt = 0; mt < 4; ++mt) {
                int row = wm * 64 + mt * 16 + (quad & 1) * 8 + lrow;
                int col = ks * 16 + (quad >> 1) * 8;
                ldsm_x4(af[mt][0], af[mt][1], af[mt][2], af[mt][3],
                        smem_u32(&As[row * 40 + col]));
            }
            unsigned bf[4][2];
            #pragma unroll
            for (int ntp = 0; ntp < 2; ++ntp) {
                int n0 = wn * 32 + ntp * 16;
                int kk = ks * 16 + (quad & 1) * 8 + lrow;
                int col = n0 + (quad >> 1) * 8;
                unsigned r0, r1, r2, r3;
                ldsm_x4_t(r0, r1, r2, r3, smem_u32(&Bs[kk * 136 + col]));
                bf[ntp * 2][0] = r0; bf[ntp * 2][1] = r1;
                bf[ntp * 2 + 1][0] = r2; bf[ntp * 2 + 1][1] = r3;
            }
            #pragma unroll
            for (int mt = 0; mt < 4; ++mt)
                #pragma unroll
                for (int nt = 0; nt < 4; ++nt)
                    mma16(acc[mt][nt], af[mt], bf[nt]);
        }
    }

    #pragma unroll
    for (int mt = 0; mt < 4; ++mt) {
        #pragma unroll
        for (int nt = 0; nt < 4; ++nt) {
            int row = bm + wm * 64 + mt * 16 + r;
            int cc  = bn + wn * 32 + nt * 8 + 2 * c;
            float b0 = bias[cc], b1 = bias[cc + 1];
            C[(size_t)row * N + cc]           = (acc[mt][nt][0] + b0) * scale;
            C[(size_t)row * N + cc + 1]       = (acc[mt][nt][1] + b1) * scale;
            C[(size_t)(row + 8) * N + cc]     = (acc[mt][nt][2] + b0) * scale;
            C[(size_t)(row + 8) * N + cc + 1] = (acc[mt][nt][3] + b1) * scale;
        }
    }
}

// ---------------- RoPE kernels (emit fp16) ------------------------------------
__global__ void rope_q_kernel(const float* __restrict__ tmpq,
                              const float* __restrict__ posq,
                              __half* __restrict__ qout) {
    int idx = blockIdx.x * blockDim.x + threadIdx.x;
    if (idx >= BB * LQ_ * HID_) return;
    int d = idx & 63;
    int h = (idx >> 6) & 15;
    int t = (idx >> 10) & 2047;
    int b = idx >> 21;
    float x  = tmpq[idx];
    float xp = tmpq[idx ^ 32];
    float rh = (d < 32) ? -xp : xp;
    float p  = posq[b * LQ_ + t];
    int j = d & 31;
    float invf = expf(-(float)j * 0.28782313662425572f);
    float ph = p * invf;
    float out = x * cosf(ph) + rh * sinf(ph);
    qout[(((size_t)(b * NH_ + h)) * LQ_ + t) * HD_ + d] = __float2half(out);
}

__global__ void rope_kv_kernel(const float* __restrict__ tmpkv,
                               const float* __restrict__ posk,
                               const float* __restrict__ distk,
                               __half* __restrict__ kout,
                               __half* __restrict__ vout) {
    int idx = blockIdx.x * blockDim.x + threadIdx.x;
    if (idx >= BB * LK_ * HID_) return;
    int d = idx & 63;
    int h = (idx >> 6) & 15;
    int t = (idx >> 10) & 2047;
    int b = idx >> 21;
    size_t rowbase = ((size_t)b * LK_ + t) * (2 * HID_);
    int hd = h * 64 + d;
    float x  = tmpkv[rowbase + hd];
    float xp = tmpkv[rowbase + (hd ^ 32)];
    float rh = (d < 32) ? -xp : xp;
    float p  = posk[b * LK_ + t];
    int j = d & 31;
    float invf = expf(-(float)j * 0.28782313662425572f);
    float ph = p * invf;
    int dj = (d < 32) ? d : d - 32;
    float fg = expf(-11.512925464970229f + (float)dj * 0.32666551948001156f);
    float dist = distk[b * LK_ + t];
    float arg = dist * fg;
    float demb = (d < 32) ? cosf(arg) : sinf(arg);
    float kr = x * cosf(ph) + rh * sinf(ph) + demb;
    size_t o = (((size_t)(b * NH_ + h)) * LK_ + t) * HD_ + d;
    kout[o] = __float2half(kr);
    vout[o] = __float2half(tmpkv[rowbase + HID_ + hd]);
}

// ---------------- FP16 flash attention ----------------------------------------
// CTA: 128 q rows, 8 warps (16 rows each). K tiles of 64, double buffered.
// Row pitch 72 halves (144B, 36-word stride: conflict-free ldmatrix).
#define AP 72
__global__ __launch_bounds__(256) void attn_h_kernel(
    const __half* __restrict__ Qg, const __half* __restrict__ Kg,
    const __half* __restrict__ Vg, const int* __restrict__ validk,
    const int* __restrict__ validq, __half* __restrict__ Og)
{
    extern __shared__ __half sh[];
    __half* Qs  = sh;                         // 128*72
    __half* Ksb = Qs + 128 * AP;              // 2 * 64*72
    __half* Vsb = Ksb + 2 * 64 * AP;          // 2 * 64*72
    float*  madb = (float*)(Vsb + 2 * 64 * AP); // 2 * 64

    const int qt = blockIdx.x, h = blockIdx.y, b = blockIdx.z;
    const int tid = threadIdx.x, lane = tid & 31, wid = tid >> 5;
    const int r = lane >> 2, c = lane & 3;
    const int quad = lane >> 3, lrow = lane & 7;

    const __half* Qb = Qg + (((size_t)(b * NH_ + h)) * LQ_ + qt * 128) * HD_;
    const __half* Kb = Kg + ((size_t)(b * NH_ + h)) * LK_ * HD_;
    const __half* Vb = Vg + ((size_t)(b * NH_ + h)) * LK_ * HD_;

    auto issue_tile = [&](int kt, int buf) {
        const __half* Kt = Kb + (size_t)kt * 64 * HD_;
        const __half* Vt = Vb + (size_t)kt * 64 * HD_;
        __half* Kd = Ksb + buf * 64 * AP;
        __half* Vd = Vsb + buf * 64 * AP;
        #pragma unroll
        for (int j = 0; j < 2; ++j) {
            int idx = tid + j * 256;               // 512 chunks each
            int row = idx >> 3, c16 = idx & 7;
            cpa16(Kd + row * AP + c16 * 8, Kt + row * 64 + c16 * 8);
            cpa16(Vd + row * AP + c16 * 8, Vt + row * 64 + c16 * 8);
        }
        if (tid < 64)
            madb[buf * 64 + tid] = validk[b * LK_ + kt * 64 + tid] ? 0.0f : -1e9f;
    };

    // prologue: Q + tile 0 in one group
    #pragma unroll
    for (int j = 0; j < 4; ++j) {
        int idx = tid + j * 256;                   // 1024 chunks
        int row = idx >> 3, c16 = idx & 7;
        cpa16(Qs + row * AP + c16 * 8, Qb + row * 64 + c16 * 8);
    }
    issue_tile(0, 0);
    CPA_COMMIT();

    float O[8][4] = {};
    float mrow[2] = {-1e30f, -1e30f};
    float lrow2[2] = {0.f, 0.f};
    unsigned qf[4][4];
    bool qloaded = false;

    for (int kt = 0; kt < NKT; ++kt) {
        int buf = kt & 1;
        __syncthreads();
        if (kt + 1 < NKT) { issue_tile(kt + 1, buf ^ 1); CPA_COMMIT(); CPA_WAIT1(); }
        else             { CPA_WAIT0(); }
        __syncthreads();

        if (!qloaded) {
            qloaded = true;
            #pragma unroll
            for (int ks = 0; ks < 4; ++ks) {
                int row = wid * 16 + (quad & 1) * 8 + lrow;
                int col = ks * 16 + (quad >> 1) * 8;
                ldsm_x4(qf[ks][0], qf[ks][1], qf[ks][2], qf[ks][3],
                        smem_u32(&Qs[row * AP + col]));
            }
        }

        const __half* Ks = Ksb + buf * 64 * AP;
        const __half* Vs = Vsb + buf * 64 * AP;
        const float* madd = madb + buf * 64;

        // ---- S = Q K^T ----  (B-frag: non-trans ldmatrix on K rows)
        float S[8][4] = {};
        #pragma unroll
        for (int ks = 0; ks < 4; ++ks) {
            #pragma unroll
            for (int ntp = 0; ntp < 4; ++ntp) {
                int n0 = ntp * 16;
                int row = n0 + (quad >> 1) * 8 + lrow;
                int col = ks * 16 + (quad & 1) * 8;
                unsigned r0, r1, r2, r3;
                ldsm_x4(r0, r1, r2, r3, smem_u32(&Ks[row * AP + col]));
                unsigned bf0[2] = {r0, r1}, bf1[2] = {r2, r3};
                mma16(S[ntp * 2],     qf[ks], bf0);
                mma16(S[ntp * 2 + 1], qf[ks], bf1);
            }
        }

        // ---- mask + online softmax ----
        float m0 = mrow[0], m1 = mrow[1];
        #pragma unroll
        for (int nt = 0; nt < 8; ++nt) {
            float2 mv = *(const float2*)&madd[nt * 8 + 2 * c];
            S[nt][0] += mv.x; S[nt][1] += mv.y;
            S[nt][2] += mv.x; S[nt][3] += mv.y;
            m0 = fmaxf(m0, fmaxf(S[nt][0], S[nt][1]));
            m1 = fmaxf(m1, fmaxf(S[nt][2], S[nt][3]));
        }
        m0 = fmaxf(m0, __shfl_xor_sync(0xffffffffu, m0, 1));
        m0 = fmaxf(m0, __shfl_xor_sync(0xffffffffu, m0, 2));
        m1 = fmaxf(m1, __shfl_xor_sync(0xffffffffu, m1, 1));
        m1 = fmaxf(m1, __shfl_xor_sync(0xffffffffu, m1, 2));
        float a0 = __expf(mrow[0] - m0), a1 = __expf(mrow[1] - m1);
        mrow[0] = m0; mrow[1] = m1;

        float ls0 = 0.f, ls1 = 0.f;
        #pragma unroll
        for (int nt = 0; nt < 8; ++nt) {
            S[nt][0] = __expf(S[nt][0] - m0);
            S[nt][1] = __expf(S[nt][1] - m0);
            S[nt][2] = __expf(S[nt][2] - m1);
            S[nt][3] = __expf(S[nt][3] - m1);
            ls0 += S[nt][0] + S[nt][1];
            ls1 += S[nt][2] + S[nt][3];
        }
        ls0 += __shfl_xor_sync(0xffffffffu, ls0, 1);
        ls0 += __shfl_xor_sync(0xffffffffu, ls0, 2);
        ls1 += __shfl_xor_sync(0xffffffffu, ls1, 1);
        ls1 += __shfl_xor_sync(0xffffffffu, ls1, 2);
        lrow2[0] = lrow2[0] * a0 + ls0;
        lrow2[1] = lrow2[1] * a1 + ls1;

        #pragma unroll
        for (int nt = 0; nt < 8; ++nt) {
            O[nt][0] *= a0; O[nt][1] *= a0; O[nt][2] *= a1; O[nt][3] *= a1;
        }

        // ---- O += P V ----  (A-frag = packed S C-frag; B-frag: trans ldmatrix on V)
        #pragma unroll
        for (int ksp = 0; ksp < 4; ++ksp) {
            unsigned a[4];
            a[0] = pack2h(S[2 * ksp][0],     S[2 * ksp][1]);
            a[1] = pack2h(S[2 * ksp][2],     S[2 * ksp][3]);
            a[2] = pack2h(S[2 * ksp + 1][0], S[2 * ksp + 1][1]);
            a[3] = pack2h(S[2 * ksp + 1][2], S[2 * ksp + 1][3]);
            #pragma unroll
            for (int ntp = 0; ntp < 4; ++ntp) {
                int n0 = ntp * 16;
                int row = ksp * 16 + (quad & 1) * 8 + lrow;
                int col = n0 + (quad >> 1) * 8;
                unsigned r0, r1, r2, r3;
                ldsm_x4_t(r0, r1, r2, r3, smem_u32(&Vs[row * AP + col]));
                unsigned bf0[2] = {r0, r1}, bf1[2] = {r2, r3};
                mma16(O[ntp * 2],     a, bf0);
                mma16(O[ntp * 2 + 1], a, bf1);
            }
        }
    }

    // ---- epilogue: fp16 output (feeds O-proj) ----
    int row0 = qt * 128 + wid * 16 + r;
    int vq0 = validq[b * LQ_ + row0];
    int vq1 = validq[b * LQ_ + row0 + 8];
    float inv0 = vq0 ? 1.0f / lrow2[0] : 0.0f;
    float inv1 = vq1 ? 1.0f / lrow2[1] : 0.0f;
    __half* Ob0 = Og + ((size_t)b * LQ_ + row0) * HID_ + h * 64;
    __half* Ob1 = Ob0 + 8 * HID_;
    #pragma unroll
    for (int nt = 0; nt < 8; ++nt) {
        int cc = nt * 8 + 2 * c;
        *(__half2*)&Ob0[cc] = __floats2half2_rn(O[nt][0] * inv0, O[nt][1] * inv0);
        *(__half2*)&Ob1[cc] = __floats2half2_rn(O[nt][2] * inv1, O[nt][3] * inv1);
    }
}

// ---------------- launch -----------------------------------------------------
extern "C" void kernel_launch(void* const* d_in, const int* in_sizes, int n_in,
                              void* d_out, int out_size) {
    const float* q_states  = (const float*)d_in[0];
    const float* kv_states = (const float*)d_in[1];
    const float* distances = (const float*)d_in[2];
    const int*   mask_q    = (const int*)d_in[3];
    const int*   mask_kv   = (const int*)d_in[4];
    const float* Wq        = (const float*)d_in[5];
    const float* bq        = (const float*)d_in[6];
    const float* Wkv       = (const float*)d_in[7];
    const float* bkv       = (const float*)d_in[8];
    const float* Wo        = (const float*)d_in[9];
    const float* bo        = (const float*)d_in[10];
    float* out = (float*)d_out;

    float *p_tmpq, *p_tmpkv, *p_posq, *p_posk, *p_distk;
    __half *p_qh, *p_kh, *p_vh, *p_atth, *p_aqh, *p_akvh, *p_wqh, *p_wkvh, *p_woh;
    int *p_boundq, *p_boundk, *p_validq, *p_validk;
    cudaGetSymbolAddress((void**)&p_tmpq,  g_tmpq);
    cudaGetSymbolAddress((void**)&p_tmpkv, g_tmpkv);
    cudaGetSymbolAddress((void**)&p_qh,    g_qh);
    cudaGetSymbolAddress((void**)&p_kh,    g_kh);
    cudaGetSymbolAddress((void**)&p_vh,    g_vh);
    cudaGetSymbolAddress((void**)&p_atth,  g_atth);
    cudaGetSymbolAddress((void**)&p_aqh,   g_aqh);
    cudaGetSymbolAddress((void**)&p_akvh,  g_akvh);
    cudaGetSymbolAddress((void**)&p_wqh,   g_wqh);
    cudaGetSymbolAddress((void**)&p_wkvh,  g_wkvh);
    cudaGetSymbolAddress((void**)&p_woh,   g_woh);
    cudaGetSymbolAddress((void**)&p_posq,  g_posq);
    cudaGetSymbolAddress((void**)&p_posk,  g_posk);
    cudaGetSymbolAddress((void**)&p_distk, g_distk);
    cudaGetSymbolAddress((void**)&p_boundq, g_boundq);
    cudaGetSymbolAddress((void**)&p_boundk, g_boundk);
    cudaGetSymbolAddress((void**)&p_validq, g_validq);
    cudaGetSymbolAddress((void**)&p_validk, g_validk);

    cumsum_kernel<<<BB, 1024>>>(mask_q,  p_boundq, LQ_);
    cumsum_kernel<<<BB, 1024>>>(mask_kv, p_boundk, LK_);
    posval_kernel<<<(BB * LQ_ + 255) / 256, 256>>>(mask_q,  p_boundq, nullptr,   p_posq, p_validq, nullptr, LQ_);
    posval_kernel<<<(BB * LK_ + 255) / 256, 256>>>(mask_kv, p_boundk, distances, p_posk, p_validk, p_distk, LK_);

    // pre-convert inputs + weights to fp16
    cvt_h_kernel<<<(BB*LQ_*HID_/4 + 255)/256, 256>>>(q_states,  p_aqh,  BB*LQ_*HID_/4);
    cvt_h_kernel<<<(BB*LK_*HID_/4 + 255)/256, 256>>>(kv_states, p_akvh, BB*LK_*HID_/4);
    cvt_h_kernel<<<(HID_*HID_/4 + 255)/256, 256>>>(Wq,  p_wqh,  HID_*HID_/4);
    cvt_h_kernel<<<(HID_*2*HID_/4 + 255)/256, 256>>>(Wkv, p_wkvh, HID_*2*HID_/4);
    cvt_h_kernel<<<(HID_*HID_/4 + 255)/256, 256>>>(Wo,  p_woh,  HID_*HID_/4);

    // projections (fp16 tensor cores)
    dim3 gq(HID_ / 128, BB * LQ_ / 128);
    hgemm_kernel<<<gq, 256>>>(p_aqh, p_wqh, bq, p_tmpq, BB * LQ_, HID_, HID_, 0.125f);
    dim3 gkv(2 * HID_ / 128, BB * LK_ / 128);
    hgemm_kernel<<<gkv, 256>>>(p_akvh, p_wkvh, bkv, p_tmpkv, BB * LK_, 2 * HID_, HID_, 1.0f);

    rope_q_kernel <<<BB * LQ_ * HID_ / 256, 256>>>(p_tmpq, p_posq, p_qh);
    rope_kv_kernel<<<BB * LK_ * HID_ / 256, 256>>>(p_tmpkv, p_posk, p_distk, p_kh, p_vh);

    // attention (fp16 tensor cores)
    size_t smem = (size_t)(128 * AP + 2 * 64 * AP + 2 * 64 * AP) * 2 + 2 * 64 * 4;
    cudaFuncSetAttribute(attn_h_kernel, cudaFuncAttributeMaxDynamicSharedMemorySize, (int)smem);
    attn_h_kernel<<<dim3(LQ_ / 128, NH_, BB), 256, smem>>>(p_qh, p_kh, p_vh, p_validk, p_validq, p_atth);

    // output projection
    hgemm_kernel<<<gq, 256>>>(p_atth, p_woh, bo, out, BB * LQ_, HID_, HID_, 1.0f);
}

// round 5
// speedup vs baseline: 6.3377x; 1.1622x over previous
#include <cuda_runtime.h>
#include <cuda_fp16.h>
#include <math.h>

#define BB   2
#define LQ_  2048
#define LK_  2048
#define HID_ 1024
#define NH_  16
#define HD_  64
#define NKT  (LK_/64)

// ---------------- scratch ----------------------------------------------------
__device__ float  g_tmpq [BB*LQ_*HID_];
__device__ float  g_tmpkv[BB*LK_*2*HID_];
__device__ __half g_qh [BB*NH_*LQ_*HD_];
__device__ __half g_kh [BB*NH_*LK_*HD_];
__device__ __half g_vh [BB*NH_*LK_*HD_];
__device__ __half g_atth[BB*LQ_*HID_];
__device__ __half g_aqh [BB*LQ_*HID_];
__device__ __half g_akvh[BB*LK_*HID_];
__device__ __half g_wqh [HID_*HID_];
__device__ __half g_wkvh[HID_*2*HID_];
__device__ __half g_woh [HID_*HID_];
__device__ float  g_posq[BB*LQ_];
__device__ float  g_posk[BB*LK_];
__device__ float  g_distk[BB*LK_];
__device__ int    g_validq[BB*LQ_];
__device__ int    g_validk[BB*LK_];

// ---------------- helpers ----------------------------------------------------
__device__ __forceinline__ unsigned smem_u32(const void* p) {
    return (unsigned)__cvta_generic_to_shared(p);
}
__device__ __forceinline__ void ldsm_x4(unsigned& r0, unsigned& r1, unsigned& r2, unsigned& r3, unsigned a) {
    asm volatile("ldmatrix.sync.aligned.m8n8.x4.shared.b16 {%0,%1,%2,%3}, [%4];"
                 : "=r"(r0), "=r"(r1), "=r"(r2), "=r"(r3) : "r"(a));
}
__device__ __forceinline__ void ldsm_x4_t(unsigned& r0, unsigned& r1, unsigned& r2, unsigned& r3, unsigned a) {
    asm volatile("ldmatrix.sync.aligned.m8n8.x4.trans.shared.b16 {%0,%1,%2,%3}, [%4];"
                 : "=r"(r0), "=r"(r1), "=r"(r2), "=r"(r3) : "r"(a));
}
__device__ __forceinline__ void mma16(float* c, const unsigned* a, const unsigned* b) {
    asm volatile(
        "mma.sync.aligned.m16n8k16.row.col.f32.f16.f16.f32 "
        "{%0,%1,%2,%3}, {%4,%5,%6,%7}, {%8,%9}, {%0,%1,%2,%3};"
        : "+f"(c[0]), "+f"(c[1]), "+f"(c[2]), "+f"(c[3])
        : "r"(a[0]), "r"(a[1]), "r"(a[2]), "r"(a[3]), "r"(b[0]), "r"(b[1]));
}
__device__ __forceinline__ unsigned pack2h(float x, float y) {
    __half2 h = __floats2half2_rn(x, y);
    return *(unsigned*)&h;
}
__device__ __forceinline__ void cpa16(void* sdst, const void* gsrc) {
    unsigned sa = smem_u32(sdst);
    asm volatile("cp.async.cg.shared.global [%0], [%1], 16;" :: "r"(sa), "l"(gsrc));
}
#define CPA_COMMIT() asm volatile("cp.async.commit_group;" ::: "memory")
#define CPA_WAIT1()  asm volatile("cp.async.wait_group 1;" ::: "memory")
#define CPA_WAIT0()  asm volatile("cp.async.wait_group 0;" ::: "memory")

// ---------------- fused segment geometry (scan + positions) -------------------
// 4 blocks: 0,1 = q side (b=0,1); 2,3 = kv side (b=0,1). 1024 threads.
__global__ void geom_kernel(const int* __restrict__ mask_q, const int* __restrict__ mask_kv,
                            const float* __restrict__ distances,
                            float* __restrict__ posq, int* __restrict__ validq,
                            float* __restrict__ posk, int* __restrict__ validk,
                            float* __restrict__ distk) {
    __shared__ int sa[2048], sb[2048];
    const int bi = blockIdx.x;
    const int side = (bi >> 1);            // 0 = q, 1 = kv
    const int b = bi & 1;
    const int L = side ? LK_ : LQ_;
    const int* mask = (side ? mask_kv : mask_q) + b * L;
    const int tid = threadIdx.x;

    for (int i = tid; i < L; i += 1024) sa[i] = mask[i];
    __syncthreads();
    int* cur = sa; int* nxt = sb;
    for (int off = 1; off < L; off <<= 1) {
        for (int i = tid; i < L; i += 1024)
            nxt[i] = cur[i] + (i >= off ? cur[i - off] : 0);
        __syncthreads();
        int* t = cur; cur = nxt; nxt = t;
    }
    const int total = cur[L - 1];
    for (int t = tid; t < L; t += 1024) {
        int lo = 0, hi = L;
        while (lo < hi) { int mid = (lo + hi) >> 1; if (cur[mid] <= t) lo = mid + 1; else hi = mid; }
        int seg = lo < (L - 1) ? lo : (L - 1);
        int v = (t < total) ? 1 : 0;
        int start = cur[seg] - mask[seg];
        float p = v ? (float)(t - start) : 0.0f;
        if (side == 0) {
            posq[b * L + t] = p; validq[b * L + t] = v;
        } else {
            posk[b * L + t] = p; validk[b * L + t] = v;
            distk[b * L + t] = v ? distances[b * L + seg] : 0.0f;
        }
    }
}

// ---------------- fused f32 -> f16 conversion (all 5 tensors) -----------------
#define N4_AQ  (BB*LQ_*HID_/4)
#define N4_AKV (BB*LK_*HID_/4)
#define N4_WQ  (HID_*HID_/4)
#define N4_WKV (HID_*2*HID_/4)
#define N4_WO  (HID_*HID_/4)
#define N4_TOT (N4_AQ + N4_AKV + N4_WQ + N4_WKV + N4_WO)
__global__ void cvt_all_kernel(const float* __restrict__ aq, const float* __restrict__ akv,
                               const float* __restrict__ wq, const float* __restrict__ wkv,
                               const float* __restrict__ wo,
                               __half* __restrict__ daq, __half* __restrict__ dakv,
                               __half* __restrict__ dwq, __half* __restrict__ dwkv,
                               __half* __restrict__ dwo) {
    int i = blockIdx.x * blockDim.x + threadIdx.x;
    if (i >= N4_TOT) return;
    const float* src; __half* dst; int off;
    if (i < N4_AQ)                              { src = aq;  dst = daq;  off = i; }
    else if (i < N4_AQ + N4_AKV)                { src = akv; dst = dakv; off = i - N4_AQ; }
    else if (i < N4_AQ + N4_AKV + N4_WQ)        { src = wq;  dst = dwq;  off = i - N4_AQ - N4_AKV; }
    else if (i < N4_AQ + N4_AKV + N4_WQ + N4_WKV) { src = wkv; dst = dwkv; off = i - N4_AQ - N4_AKV - N4_WQ; }
    else                                        { src = wo;  dst = dwo;  off = i - N4_AQ - N4_AKV - N4_WQ - N4_WKV; }
    float4 v = ((const float4*)src)[off];
    ((__half2*)dst)[off * 2]     = __floats2half2_rn(v.x, v.y);
    ((__half2*)dst)[off * 2 + 1] = __floats2half2_rn(v.z, v.w);
}

// ---------------- FP16 GEMM, 3-stage cp.async ring ----------------------------
// A: MxK row-major half, B: KxN row-major half. CTA 128x128, k-chunk 32.
#define GAP 40
#define GBP 136
#define GA_STG (128 * GAP)
#define GB_STG (32 * GBP)
__global__ __launch_bounds__(256) void hgemm_kernel(
    const __half* __restrict__ A, const __half* __restrict__ Bm,
    const float* __restrict__ bias, float* __restrict__ C,
    int M, int N, int K, float scale)
{
    extern __shared__ __half gsh[];
    __half* Asb = gsh;                 // 3 stages of 128x40
    __half* Bsb = gsh + 3 * GA_STG;    // 3 stages of 32x136
    const int tid = threadIdx.x, lane = tid & 31, wid = tid >> 5;
    const int wm = wid >> 2, wn = wid & 3;
    const int r = lane >> 2, c = lane & 3;
    const int quad = lane >> 3, lrow = lane & 7;
    const int bm = blockIdx.y * 128, bn = blockIdx.x * 128;
    const __half* Ag = A + (size_t)bm * K;

    float acc[4][4][4] = {};

    auto issue = [&](int kc, int buf) {
        __half* Ad = Asb + buf * GA_STG;
        __half* Bd = Bsb + buf * GB_STG;
        #pragma unroll
        for (int j = 0; j < 2; ++j) {
            int idx = tid + j * 256;
            int row = idx >> 2, c16 = idx & 3;
            cpa16(Ad + row * GAP + c16 * 8, Ag + (size_t)row * K + kc * 32 + c16 * 8);
        }
        #pragma unroll
        for (int j = 0; j < 2; ++j) {
            int idx = tid + j * 256;
            int kk = idx >> 4, c16 = idx & 15;
            cpa16(Bd + kk * GBP + c16 * 8, Bm + (size_t)(kc * 32 + kk) * N + bn + c16 * 8);
        }
    };

    const int NKC = K / 32;
    issue(0, 0); CPA_COMMIT();
    issue(1, 1); CPA_COMMIT();

    for (int kc = 0; kc < NKC; ++kc) {
        CPA_WAIT1();                      // chunk kc landed
        __syncthreads();                  // everyone done with (kc-1)'s buffer
        if (kc + 2 < NKC) { issue(kc + 2, (kc + 2) % 3); CPA_COMMIT(); }

        const __half* As = Asb + (kc % 3) * GA_STG;
        const __half* Bs = Bsb + (kc % 3) * GB_STG;
        #pragma unroll
        for (int ks = 0; ks < 2; ++ks) {
            unsigned af[4][4];
            #pragma unroll
            for (int mt = 0; mt < 4; ++mt) {
                int row = wm * 64 + mt * 16 + (quad & 1) * 8 + lrow;
                int col = ks * 16 + (quad >> 1) * 8;
                ldsm_x4(af[mt][0], af[mt][1], af[mt][2], af[mt][3],
                        smem_u32(&As[row * GAP + col]));
            }
            unsigned bf[4][2];
            #pragma unroll
            for (int ntp = 0; ntp < 2; ++ntp) {
                int n0 = wn * 32 + ntp * 16;
                int kk = ks * 16 + (quad & 1) * 8 + lrow;
                int col = n0 + (quad >> 1) * 8;
                unsigned r0, r1, r2, r3;
                ldsm_x4_t(r0, r1, r2, r3, smem_u32(&Bs[kk * GBP + col]));
                bf[ntp * 2][0] = r0; bf[ntp * 2][1] = r1;
                bf[ntp * 2 + 1][0] = r2; bf[ntp * 2 + 1][1] = r3;
            }
            #pragma unroll
            for (int mt = 0; mt < 4; ++mt)
                #pragma unroll
                for (int nt = 0; nt < 4; ++nt)
                    mma16(acc[mt][nt], af[mt], bf[nt]);
        }
    }

    #pragma unroll
    for (int mt = 0; mt < 4; ++mt) {
        #pragma unroll
        for (int nt = 0; nt < 4; ++nt) {
            int row = bm + wm * 64 + mt * 16 + r;
            int cc  = bn + wn * 32 + nt * 8 + 2 * c;
            float b0 = bias[cc], b1 = bias[cc + 1];
            C[(size_t)row * N + cc]           = (acc[mt][nt][0] + b0) * scale;
            C[(size_t)row * N + cc + 1]       = (acc[mt][nt][1] + b1) * scale;
            C[(size_t)(row + 8) * N + cc]     = (acc[mt][nt][2] + b0) * scale;
            C[(size_t)(row + 8) * N + cc + 1] = (acc[mt][nt][3] + b1) * scale;
        }
    }
}

// ---------------- fused RoPE (q + kv) -----------------------------------------
#define NQE (BB*LQ_*HID_)
#define NKE (BB*LK_*HID_)
__global__ void rope_all_kernel(const float* __restrict__ tmpq,
                                const float* __restrict__ tmpkv,
                                const float* __restrict__ posq,
                                const float* __restrict__ posk,
                                const float* __restrict__ distk,
                                __half* __restrict__ qout,
                                __half* __restrict__ kout,
                                __half* __restrict__ vout) {
    int gi = blockIdx.x * blockDim.x + threadIdx.x;
    if (gi < NQE) {
        int idx = gi;
        int d = idx & 63;
        int h = (idx >> 6) & 15;
        int t = (idx >> 10) & 2047;
        int b = idx >> 21;
        float x  = tmpq[idx];
        float xp = tmpq[idx ^ 32];
        float rh = (d < 32) ? -xp : xp;
        float p  = posq[b * LQ_ + t];
        int j = d & 31;
        float invf = expf(-(float)j * 0.28782313662425572f);
        float ph = p * invf;
        float out = x * cosf(ph) + rh * sinf(ph);
        qout[(((size_t)(b * NH_ + h)) * LQ_ + t) * HD_ + d] = __float2half(out);
    } else if (gi < NQE + NKE) {
        int idx = gi - NQE;
        int d = idx & 63;
        int h = (idx >> 6) & 15;
        int t = (idx >> 10) & 2047;
        int b = idx >> 21;
        size_t rowbase = ((size_t)b * LK_ + t) * (2 * HID_);
        int hd = h * 64 + d;
        float x  = tmpkv[rowbase + hd];
        float xp = tmpkv[rowbase + (hd ^ 32)];
        float rh = (d < 32) ? -xp : xp;
        float p  = posk[b * LK_ + t];
        int j = d & 31;
        float invf = expf(-(float)j * 0.28782313662425572f);
        float ph = p * invf;
        int dj = (d < 32) ? d : d - 32;
        float fg = expf(-11.512925464970229f + (float)dj * 0.32666551948001156f);
        float dist = distk[b * LK_ + t];
        float arg = dist * fg;
        float demb = (d < 32) ? cosf(arg) : sinf(arg);
        float kr = x * cosf(ph) + rh * sinf(ph) + demb;
        size_t o = (((size_t)(b * NH_ + h)) * LK_ + t) * HD_ + d;
        kout[o] = __float2half(kr);
        vout[o] = __float2half(tmpkv[rowbase + HID_ + hd]);
    }
}

// ---------------- FP16 flash attention (unchanged, known-good) ----------------
#define AP 72
__global__ __launch_bounds__(256) void attn_h_kernel(
    const __half* __restrict__ Qg, const __half* __restrict__ Kg,
    const __half* __restrict__ Vg, const int* __restrict__ validk,
    const int* __restrict__ validq, __half* __restrict__ Og)
{
    extern __shared__ __half sh[];
    __half* Qs  = sh;                           // 128*72
    __half* Ksb = Qs + 128 * AP;                // 2 * 64*72
    __half* Vsb = Ksb + 2 * 64 * AP;            // 2 * 64*72
    float*  madb = (float*)(Vsb + 2 * 64 * AP); // 2 * 64

    const int qt = blockIdx.x, h = blockIdx.y, b = blockIdx.z;
    const int tid = threadIdx.x, lane = tid & 31, wid = tid >> 5;
    const int r = lane >> 2, c = lane & 3;
    const int quad = lane >> 3, lrow = lane & 7;

    const __half* Qb = Qg + (((size_t)(b * NH_ + h)) * LQ_ + qt * 128) * HD_;
    const __half* Kb = Kg + ((size_t)(b * NH_ + h)) * LK_ * HD_;
    const __half* Vb = Vg + ((size_t)(b * NH_ + h)) * LK_ * HD_;

    auto issue_tile = [&](int kt, int buf) {
        const __half* Kt = Kb + (size_t)kt * 64 * HD_;
        const __half* Vt = Vb + (size_t)kt * 64 * HD_;
        __half* Kd = Ksb + buf * 64 * AP;
        __half* Vd = Vsb + buf * 64 * AP;
        #pragma unroll
        for (int j = 0; j < 2; ++j) {
            int idx = tid + j * 256;
            int row = idx >> 3, c16 = idx & 7;
            cpa16(Kd + row * AP + c16 * 8, Kt + row * 64 + c16 * 8);
            cpa16(Vd + row * AP + c16 * 8, Vt + row * 64 + c16 * 8);
        }
        if (tid < 64)
            madb[buf * 64 + tid] = validk[b * LK_ + kt * 64 + tid] ? 0.0f : -1e9f;
    };

    #pragma unroll
    for (int j = 0; j < 4; ++j) {
        int idx = tid + j * 256;
        int row = idx >> 3, c16 = idx & 7;
        cpa16(Qs + row * AP + c16 * 8, Qb + row * 64 + c16 * 8);
    }
    issue_tile(0, 0);
    CPA_COMMIT();

    float O[8][4] = {};
    float mrow[2] = {-1e30f, -1e30f};
    float lrow2[2] = {0.f, 0.f};
    unsigned qf[4][4];
    bool qloaded = false;

    for (int kt = 0; kt < NKT; ++kt) {
        int buf = kt & 1;
        __syncthreads();
        if (kt + 1 < NKT) { issue_tile(kt + 1, buf ^ 1); CPA_COMMIT(); CPA_WAIT1(); }
        else             { CPA_WAIT0(); }
        __syncthreads();

        if (!qloaded) {
            qloaded = true;
            #pragma unroll
            for (int ks = 0; ks < 4; ++ks) {
                int row = wid * 16 + (quad & 1) * 8 + lrow;
                int col = ks * 16 + (quad >> 1) * 8;
                ldsm_x4(qf[ks][0], qf[ks][1], qf[ks][2], qf[ks][3],
                        smem_u32(&Qs[row * AP + col]));
            }
        }

        const __half* Ks = Ksb + buf * 64 * AP;
        const __half* Vs = Vsb + buf * 64 * AP;
        const float* madd = madb + buf * 64;

        float S[8][4] = {};
        #pragma unroll
        for (int ks = 0; ks < 4; ++ks) {
            #pragma unroll
            for (int ntp = 0; ntp < 4; ++ntp) {
                int n0 = ntp * 16;
                int row = n0 + (quad >> 1) * 8 + lrow;
                int col = ks * 16 + (quad & 1) * 8;
                unsigned r0, r1, r2, r3;
                ldsm_x4(r0, r1, r2, r3, smem_u32(&Ks[row * AP + col]));
                unsigned bf0[2] = {r0, r1}, bf1[2] = {r2, r3};
                mma16(S[ntp * 2],     qf[ks], bf0);
                mma16(S[ntp * 2 + 1], qf[ks], bf1);
            }
        }

        float m0 = mrow[0], m1 = mrow[1];
        #pragma unroll
        for (int nt = 0; nt < 8; ++nt) {
            float2 mv = *(const float2*)&madd[nt * 8 + 2 * c];
            S[nt][0] += mv.x; S[nt][1] += mv.y;
            S[nt][2] += mv.x; S[nt][3] += mv.y;
            m0 = fmaxf(m0, fmaxf(S[nt][0], S[nt][1]));
            m1 = fmaxf(m1, fmaxf(S[nt][2], S[nt][3]));
        }
        m0 = fmaxf(m0, __shfl_xor_sync(0xffffffffu, m0, 1));
        m0 = fmaxf(m0, __shfl_xor_sync(0xffffffffu, m0, 2));
        m1 = fmaxf(m1, __shfl_xor_sync(0xffffffffu, m1, 1));
        m1 = fmaxf(m1, __shfl_xor_sync(0xffffffffu, m1, 2));
        float a0 = __expf(mrow[0] - m0), a1 = __expf(mrow[1] - m1);
        mrow[0] = m0; mrow[1] = m1;

        float ls0 = 0.f, ls1 = 0.f;
        #pragma unroll
        for (int nt = 0; nt < 8; ++nt) {
            S[nt][0] = __expf(S[nt][0] - m0);
            S[nt][1] = __expf(S[nt][1] - m0);
            S[nt][2] = __expf(S[nt][2] - m1);
            S[nt][3] = __expf(S[nt][3] - m1);
            ls0 += S[nt][0] + S[nt][1];
            ls1 += S[nt][2] + S[nt][3];
        }
        ls0 += __shfl_xor_sync(0xffffffffu, ls0, 1);
        ls0 += __shfl_xor_sync(0xffffffffu, ls0, 2);
        ls1 += __shfl_xor_sync(0xffffffffu, ls1, 1);
        ls1 += __shfl_xor_sync(0xffffffffu, ls1, 2);
        lrow2[0] = lrow2[0] * a0 + ls0;
        lrow2[1] = lrow2[1] * a1 + ls1;

        #pragma unroll
        for (int nt = 0; nt < 8; ++nt) {
            O[nt][0] *= a0; O[nt][1] *= a0; O[nt][2] *= a1; O[nt][3] *= a1;
        }

        #pragma unroll
        for (int ksp = 0; ksp < 4; ++ksp) {
            unsigned a[4];
            a[0] = pack2h(S[2 * ksp][0],     S[2 * ksp][1]);
            a[1] = pack2h(S[2 * ksp][2],     S[2 * ksp][3]);
            a[2] = pack2h(S[2 * ksp + 1][0], S[2 * ksp + 1][1]);
            a[3] = pack2h(S[2 * ksp + 1][2], S[2 * ksp + 1][3]);
            #pragma unroll
            for (int ntp = 0; ntp < 4; ++ntp) {
                int n0 = ntp * 16;
                int row = ksp * 16 + (quad & 1) * 8 + lrow;
                int col = n0 + (quad >> 1) * 8;
                unsigned r0, r1, r2, r3;
                ldsm_x4_t(r0, r1, r2, r3, smem_u32(&Vs[row * AP + col]));
                unsigned bf0[2] = {r0, r1}, bf1[2] = {r2, r3};
                mma16(O[ntp * 2],     a, bf0);
                mma16(O[ntp * 2 + 1], a, bf1);
            }
        }
    }

    int row0 = qt * 128 + wid * 16 + r;
    int vq0 = validq[b * LQ_ + row0];
    int vq1 = validq[b * LQ_ + row0 + 8];
    float inv0 = vq0 ? 1.0f / lrow2[0] : 0.0f;
    float inv1 = vq1 ? 1.0f / lrow2[1] : 0.0f;
    __half* Ob0 = Og + ((size_t)b * LQ_ + row0) * HID_ + h * 64;
    __half* Ob1 = Ob0 + 8 * HID_;
    #pragma unroll
    for (int nt = 0; nt < 8; ++nt) {
        int cc = nt * 8 + 2 * c;
        *(__half2*)&Ob0[cc] = __floats2half2_rn(O[nt][0] * inv0, O[nt][1] * inv0);
        *(__half2*)&Ob1[cc] = __floats2half2_rn(O[nt][2] * inv1, O[nt][3] * inv1);
    }
}

// ---------------- launch -----------------------------------------------------
extern "C" void kernel_launch(void* const* d_in, const int* in_sizes, int n_in,
                              void* d_out, int out_size) {
    const float* q_states  = (const float*)d_in[0];
    const float* kv_states = (const float*)d_in[1];
    const float* distances = (const float*)d_in[2];
    const int*   mask_q    = (const int*)d_in[3];
    const int*   mask_kv   = (const int*)d_in[4];
    const float* bq        = (const float*)d_in[6];
    const float* Wq        = (const float*)d_in[5];
    const float* Wkv       = (const float*)d_in[7];
    const float* bkv       = (const float*)d_in[8];
    const float* Wo        = (const float*)d_in[9];
    const float* bo        = (const float*)d_in[10];
    float* out = (float*)d_out;

    float *p_tmpq, *p_tmpkv, *p_posq, *p_posk, *p_distk;
    __half *p_qh, *p_kh, *p_vh, *p_atth, *p_aqh, *p_akvh, *p_wqh, *p_wkvh, *p_woh;
    int *p_validq, *p_validk;
    cudaGetSymbolAddress((void**)&p_tmpq,  g_tmpq);
    cudaGetSymbolAddress((void**)&p_tmpkv, g_tmpkv);
    cudaGetSymbolAddress((void**)&p_qh,    g_qh);
    cudaGetSymbolAddress((void**)&p_kh,    g_kh);
    cudaGetSymbolAddress((void**)&p_vh,    g_vh);
    cudaGetSymbolAddress((void**)&p_atth,  g_atth);
    cudaGetSymbolAddress((void**)&p_aqh,   g_aqh);
    cudaGetSymbolAddress((void**)&p_akvh,  g_akvh);
    cudaGetSymbolAddress((void**)&p_wqh,   g_wqh);
    cudaGetSymbolAddress((void**)&p_wkvh,  g_wkvh);
    cudaGetSymbolAddress((void**)&p_woh,   g_woh);
    cudaGetSymbolAddress((void**)&p_posq,  g_posq);
    cudaGetSymbolAddress((void**)&p_posk,  g_posk);
    cudaGetSymbolAddress((void**)&p_distk, g_distk);
    cudaGetSymbolAddress((void**)&p_validq, g_validq);
    cudaGetSymbolAddress((void**)&p_validk, g_validk);

    size_t gsmem = (size_t)(3 * GA_STG + 3 * GB_STG) * sizeof(__half);  // 56832 B
    cudaFuncSetAttribute(hgemm_kernel, cudaFuncAttributeMaxDynamicSharedMemorySize, (int)gsmem);
    size_t asmem = (size_t)(128 * AP + 4 * 64 * AP) * sizeof(__half) + 2 * 64 * sizeof(float);
    cudaFuncSetAttribute(attn_h_kernel, cudaFuncAttributeMaxDynamicSharedMemorySize, (int)asmem);

    // L0: fused geometry
    geom_kernel<<<4, 1024>>>(mask_q, mask_kv, distances, p_posq, p_validq, p_posk, p_validk, p_distk);
    // L1: fused conversions
    cvt_all_kernel<<<(N4_TOT + 255) / 256, 256>>>(q_states, kv_states, Wq, Wkv, Wo,
                                                  p_aqh, p_akvh, p_wqh, p_wkvh, p_woh);
    // L2, L3: projections
    dim3 gq(HID_ / 128, BB * LQ_ / 128);
    hgemm_kernel<<<gq, 256, gsmem>>>(p_aqh, p_wqh, bq, p_tmpq, BB * LQ_, HID_, HID_, 0.125f);
    dim3 gkv(2 * HID_ / 128, BB * LK_ / 128);
    hgemm_kernel<<<gkv, 256, gsmem>>>(p_akvh, p_wkvh, bkv, p_tmpkv, BB * LK_, 2 * HID_, HID_, 1.0f);
    // L4: fused RoPE
    rope_all_kernel<<<(NQE + NKE) / 256, 256>>>(p_tmpq, p_tmpkv, p_posq, p_posk, p_distk,
                                                p_qh, p_kh, p_vh);
    // L5: attention  (ncu -s 5 -c 1 captures this one)
    attn_h_kernel<<<dim3(LQ_ / 128, NH_, BB), 256, asmem>>>(p_qh, p_kh, p_vh, p_validk, p_validq, p_atth);
    // L6: output projection
    hgemm_kernel<<<gq, 256, gsmem>>>(p_atth, p_woh, bo, out, BB * LQ_, HID_, HID_, 1.0f);
}